// round 3
// baseline (speedup 1.0000x reference)
#include <cuda_runtime.h>
#include <cuda_bf16.h>
#include <cstdint>
#include <cstddef>

// ---------------------------------------------------------------------------
// Problem constants
// ---------------------------------------------------------------------------
#define S_LEN   1500
#define N_STATE 1280
#define N_HEAD  20
#define D_HEAD  64
#define N_MLP   5120
#define NQT     24          // ceil(1500/64) query/key tiles

// ---------------------------------------------------------------------------
// Scratch (static device memory; no allocations anywhere)
// ---------------------------------------------------------------------------
struct Scratch {
    float h   [S_LEN * N_STATE];   // LN output (reused for LN1 and LN2)
    float q   [S_LEN * N_STATE];
    float k   [S_LEN * N_STATE];
    float v   [S_LEN * N_STATE];
    float attn[S_LEN * N_STATE];   // attention output pre O-proj
    float x1  [S_LEN * N_STATE];   // after attention residual
    float h2  [S_LEN * N_MLP];     // MLP hidden
};
__device__ Scratch g_scratch;

// ---------------------------------------------------------------------------
// Helpers
// ---------------------------------------------------------------------------
__device__ __forceinline__ uint32_t f2tf(float x) {
    uint32_t r;
    asm("cvt.rna.tf32.f32 %0, %1;" : "=r"(r) : "f"(x));
    return r;
}

// D = A(16x8, tf32, row) * B(8x8, tf32, col) + C, fp32 accum. In-place on acc.
__device__ __forceinline__ void mma_tf32(float acc[4], const uint32_t a[4], const uint32_t b[2]) {
    asm volatile(
        "mma.sync.aligned.m16n8k8.row.col.f32.tf32.tf32.f32 "
        "{%0,%1,%2,%3}, {%4,%5,%6,%7}, {%8,%9}, {%0,%1,%2,%3};\n"
        : "+f"(acc[0]), "+f"(acc[1]), "+f"(acc[2]), "+f"(acc[3])
        : "r"(a[0]), "r"(a[1]), "r"(a[2]), "r"(a[3]),
          "r"(b[0]), "r"(b[1]));
}

__device__ __forceinline__ float gelu_exact(float x) {
    return 0.5f * x * (1.0f + erff(x * 0.7071067811865475f));
}

// ---------------------------------------------------------------------------
// LayerNorm: one block per row, 256 threads, C = 1280 = 5*256
// ---------------------------------------------------------------------------
__global__ void ln_kernel(const float* __restrict__ x,
                          const float* __restrict__ gamma,
                          const float* __restrict__ beta,
                          float* __restrict__ out) {
    int row = blockIdx.x;
    int tid = threadIdx.x;
    const float* xr = x + (size_t)row * N_STATE;
    float* orow = out + (size_t)row * N_STATE;

    __shared__ float red[256];
    float local[5];
    float s = 0.f;
#pragma unroll
    for (int i = 0; i < 5; i++) { local[i] = xr[tid + i * 256]; s += local[i]; }
    red[tid] = s; __syncthreads();
#pragma unroll
    for (int o = 128; o > 0; o >>= 1) {
        if (tid < o) red[tid] += red[tid + o];
        __syncthreads();
    }
    float mu = red[0] * (1.0f / N_STATE);
    __syncthreads();

    float vs = 0.f;
#pragma unroll
    for (int i = 0; i < 5; i++) { float d = local[i] - mu; vs += d * d; }
    red[tid] = vs; __syncthreads();
#pragma unroll
    for (int o = 128; o > 0; o >>= 1) {
        if (tid < o) red[tid] += red[tid + o];
        __syncthreads();
    }
    float inv = rsqrtf(red[0] * (1.0f / N_STATE) + 1e-5f);

#pragma unroll
    for (int i = 0; i < 5; i++) {
        int c = tid + i * 256;
        orow[c] = (local[i] - mu) * inv * gamma[c] + beta[c];
    }
}

// ---------------------------------------------------------------------------
// tf32 MMA GEMM: C[M,N] = act(A[M,K] @ B[K,N] + bias (+ res))
//   BM=128, BN=64, BK=16, 256 threads = 8 warps (4 x 2), warp tile 32x32.
//   A smem [128][20]  -> fragment LDS banks (g*20+t)%32 all distinct: conflict-free
//   B smem [16][72]   -> fragment LDS banks (t*72+g)%32 = t*8+g: conflict-free
// ---------------------------------------------------------------------------
#define G_BM 128
#define G_BN 64
#define G_BK 16

__global__ __launch_bounds__(256)
void gemm_tf32(const float* __restrict__ A, const float* __restrict__ B,
               const float* __restrict__ bias, const float* __restrict__ res,
               float* __restrict__ C, int M, int N, int K, int act) {
    __shared__ float As[G_BM][G_BK + 4];   // stride 20
    __shared__ float Bs[G_BK][G_BN + 8];   // stride 72

    int tid  = threadIdx.x;
    int warp = tid >> 5, lane = tid & 31;
    int g = lane >> 2, t = lane & 3;
    int wm = warp >> 1;       // 0..3 -> rows wm*32
    int wn = warp & 1;        // 0..1 -> cols wn*32
    int bm0 = blockIdx.y * G_BM;
    int bn0 = blockIdx.x * G_BN;

    // global load mapping
    int arow = tid >> 2;          // 0..63 (two passes of 64 rows)
    int aq   = (tid & 3) * 4;     // k offset within tile
    int brow = tid >> 4;          // 0..15
    int bq   = (tid & 15) * 4;    // n offset within tile

    float acc[2][4][4];
#pragma unroll
    for (int i = 0; i < 2; i++)
#pragma unroll
        for (int j = 0; j < 4; j++)
#pragma unroll
            for (int r = 0; r < 4; r++) acc[i][j][r] = 0.f;

    const float4 z4 = {0.f, 0.f, 0.f, 0.f};
    float4 pa0, pa1, pb;

    auto loadg = [&](int k0) {
        int r0 = bm0 + arow, r1 = r0 + 64;
        pa0 = (r0 < M) ? *(const float4*)&A[(size_t)r0 * K + k0 + aq] : z4;
        pa1 = (r1 < M) ? *(const float4*)&A[(size_t)r1 * K + k0 + aq] : z4;
        pb  = *(const float4*)&B[(size_t)(k0 + brow) * N + bn0 + bq];
    };
    auto stores = [&]() {
        *(float4*)&As[arow][aq]      = pa0;
        *(float4*)&As[arow + 64][aq] = pa1;
        *(float4*)&Bs[brow][bq]      = pb;
    };

    int nk = K / G_BK;
    loadg(0);
    stores();
    __syncthreads();

    for (int kt = 0; kt < nk; kt++) {
        if (kt + 1 < nk) loadg((kt + 1) * G_BK);

#pragma unroll
        for (int ks = 0; ks < 2; ks++) {
            uint32_t af[2][4], bf[4][2];
#pragma unroll
            for (int i = 0; i < 2; i++) {
                int m = wm * 32 + i * 16;
                af[i][0] = f2tf(As[m + g    ][ks * 8 + t    ]);
                af[i][1] = f2tf(As[m + g + 8][ks * 8 + t    ]);
                af[i][2] = f2tf(As[m + g    ][ks * 8 + t + 4]);
                af[i][3] = f2tf(As[m + g + 8][ks * 8 + t + 4]);
            }
#pragma unroll
            for (int j = 0; j < 4; j++) {
                int n = wn * 32 + j * 8;
                bf[j][0] = f2tf(Bs[ks * 8 + t    ][n + g]);
                bf[j][1] = f2tf(Bs[ks * 8 + t + 4][n + g]);
            }
#pragma unroll
            for (int i = 0; i < 2; i++)
#pragma unroll
                for (int j = 0; j < 4; j++)
                    mma_tf32(acc[i][j], af[i], bf[j]);
        }

        __syncthreads();
        if (kt + 1 < nk) { stores(); __syncthreads(); }
    }

    // epilogue
#pragma unroll
    for (int i = 0; i < 2; i++) {
        int r0 = bm0 + wm * 32 + i * 16 + g;
        int r1 = r0 + 8;
#pragma unroll
        for (int j = 0; j < 4; j++) {
            int c = bn0 + wn * 32 + j * 8 + 2 * t;
            float bb0 = bias ? bias[c]     : 0.f;
            float bb1 = bias ? bias[c + 1] : 0.f;
            if (r0 < M) {
                float v0 = acc[i][j][0] + bb0, v1 = acc[i][j][1] + bb1;
                if (res) { v0 += res[(size_t)r0 * N + c]; v1 += res[(size_t)r0 * N + c + 1]; }
                if (act) { v0 = gelu_exact(v0); v1 = gelu_exact(v1); }
                *(float2*)&C[(size_t)r0 * N + c] = make_float2(v0, v1);
            }
            if (r1 < M) {
                float v2 = acc[i][j][2] + bb0, v3 = acc[i][j][3] + bb1;
                if (res) { v2 += res[(size_t)r1 * N + c]; v3 += res[(size_t)r1 * N + c + 1]; }
                if (act) { v2 = gelu_exact(v2); v3 = gelu_exact(v3); }
                *(float2*)&C[(size_t)r1 * N + c] = make_float2(v2, v3);
            }
        }
    }
}

// ---------------------------------------------------------------------------
// Fused flash attention (non-causal). Block = (q-tile of 64, head). 128 thr.
// Warp w owns query rows qt*64 + w*16 .. +15. Q fragments in registers
// (pre-scaled by D_HEAD^-0.5 = 0.125). Online softmax in fp32.
// P is staged through the Ks smem region (re-used after QK^T is consumed).
//   Ks stride 68: QK B-frag banks (g*68+t)%32 = g*4+t  -> conflict-free
//                 PV A-frag banks  same pattern        -> conflict-free
//   Vs stride 72: PV B-frag banks (t*72+g)%32 = t*8+g  -> conflict-free
// ---------------------------------------------------------------------------
__global__ __launch_bounds__(128)
void attn_kernel(const float* __restrict__ qp, const float* __restrict__ kp,
                 const float* __restrict__ vp, float* __restrict__ out) {
    __shared__ float Ks[64][68];   // K tile, then P (per-warp 16-row slices)
    __shared__ float Vs[64][72];

    int qt = blockIdx.x;
    int h  = blockIdx.y;
    int tid = threadIdx.x, warp = tid >> 5, lane = tid & 31;
    int g = lane >> 2, t = lane & 3;
    int qrow0 = qt * 64 + warp * 16;
    const float scale = 0.125f;   // 64^-0.5

    // ---- preload Q fragments (8 k-steps over D_HEAD=64) ----
    uint32_t qf[8][4];
    {
        int rA = qrow0 + g, rB = qrow0 + g + 8;
        bool okA = rA < S_LEN, okB = rB < S_LEN;
        const float* qA = qp + (size_t)rA * N_STATE + h * D_HEAD;
        const float* qB = qp + (size_t)rB * N_STATE + h * D_HEAD;
#pragma unroll
        for (int ks = 0; ks < 8; ks++) {
            float a0 = okA ? qA[ks * 8 + t]     : 0.f;
            float a1 = okB ? qB[ks * 8 + t]     : 0.f;
            float a2 = okA ? qA[ks * 8 + t + 4] : 0.f;
            float a3 = okB ? qB[ks * 8 + t + 4] : 0.f;
            qf[ks][0] = f2tf(a0 * scale);
            qf[ks][1] = f2tf(a1 * scale);
            qf[ks][2] = f2tf(a2 * scale);
            qf[ks][3] = f2tf(a3 * scale);
        }
    }

    float of[8][4];
#pragma unroll
    for (int j = 0; j < 8; j++)
#pragma unroll
        for (int r = 0; r < 4; r++) of[j][r] = 0.f;
    float m0 = -1e30f, m1 = -1e30f, l0 = 0.f, l1 = 0.f;

    const float4 z4 = {0.f, 0.f, 0.f, 0.f};

    for (int kt = 0; kt < NQT; kt++) {
        // ---- load K,V tile (64 keys x 64 dims), zero-pad past S_LEN ----
#pragma unroll
        for (int rep = 0; rep < 8; rep++) {
            int idx = rep * 128 + tid;
            int row = idx >> 4;
            int q4  = (idx & 15) * 4;
            int gkey = kt * 64 + row;
            float4 kv = z4, vv = z4;
            if (gkey < S_LEN) {
                kv = *(const float4*)&kp[(size_t)gkey * N_STATE + h * D_HEAD + q4];
                vv = *(const float4*)&vp[(size_t)gkey * N_STATE + h * D_HEAD + q4];
            }
            *(float4*)&Ks[row][q4] = kv;
            *(float4*)&Vs[row][q4] = vv;
        }
        __syncthreads();

        // ---- S = Q * K^T  (16 x 64 per warp) ----
        float sacc[8][4];
#pragma unroll
        for (int j = 0; j < 8; j++)
#pragma unroll
            for (int r = 0; r < 4; r++) sacc[j][r] = 0.f;

#pragma unroll
        for (int ks = 0; ks < 8; ks++) {
#pragma unroll
            for (int j = 0; j < 8; j++) {
                uint32_t bf[2];
                bf[0] = f2tf(Ks[j * 8 + g][ks * 8 + t    ]);
                bf[1] = f2tf(Ks[j * 8 + g][ks * 8 + t + 4]);
                mma_tf32(sacc[j], qf[ks], bf);
            }
        }

        // ---- mask padded keys (only last tile) ----
        if (kt == NQT - 1) {
#pragma unroll
            for (int j = 0; j < 8; j++) {
                int c = j * 8 + 2 * t;
                if (1472 + c     >= S_LEN) { sacc[j][0] = -1e30f; sacc[j][2] = -1e30f; }
                if (1472 + c + 1 >= S_LEN) { sacc[j][1] = -1e30f; sacc[j][3] = -1e30f; }
            }
        }

        // ---- online softmax ----
        float tm0 = -1e30f, tm1 = -1e30f;
#pragma unroll
        for (int j = 0; j < 8; j++) {
            tm0 = fmaxf(tm0, fmaxf(sacc[j][0], sacc[j][1]));
            tm1 = fmaxf(tm1, fmaxf(sacc[j][2], sacc[j][3]));
        }
        tm0 = fmaxf(tm0, __shfl_xor_sync(0xffffffffu, tm0, 1));
        tm0 = fmaxf(tm0, __shfl_xor_sync(0xffffffffu, tm0, 2));
        tm1 = fmaxf(tm1, __shfl_xor_sync(0xffffffffu, tm1, 1));
        tm1 = fmaxf(tm1, __shfl_xor_sync(0xffffffffu, tm1, 2));

        float nm0 = fmaxf(m0, tm0), nm1 = fmaxf(m1, tm1);
        float c0 = __expf(m0 - nm0), c1 = __expf(m1 - nm1);
        l0 *= c0; l1 *= c1;
#pragma unroll
        for (int j = 0; j < 8; j++) {
            of[j][0] *= c0; of[j][1] *= c0;
            of[j][2] *= c1; of[j][3] *= c1;
        }
        m0 = nm0; m1 = nm1;

        // wait for ALL warps to finish reading Ks before overwriting with P
        __syncthreads();

        float ps0 = 0.f, ps1 = 0.f;
#pragma unroll
        for (int j = 0; j < 8; j++) {
            float p0 = __expf(sacc[j][0] - nm0);
            float p1 = __expf(sacc[j][1] - nm0);
            float p2 = __expf(sacc[j][2] - nm1);
            float p3 = __expf(sacc[j][3] - nm1);
            ps0 += p0 + p1; ps1 += p2 + p3;
            int c = j * 8 + 2 * t;
            *(float2*)&Ks[warp * 16 + g    ][c] = make_float2(p0, p1);
            *(float2*)&Ks[warp * 16 + g + 8][c] = make_float2(p2, p3);
        }
        ps0 += __shfl_xor_sync(0xffffffffu, ps0, 1);
        ps0 += __shfl_xor_sync(0xffffffffu, ps0, 2);
        ps1 += __shfl_xor_sync(0xffffffffu, ps1, 1);
        ps1 += __shfl_xor_sync(0xffffffffu, ps1, 2);
        l0 += ps0; l1 += ps1;
        __syncwarp();

        // ---- O += P * V ----
#pragma unroll
        for (int ks = 0; ks < 8; ks++) {
            uint32_t af[4];
            af[0] = f2tf(Ks[warp * 16 + g    ][ks * 8 + t    ]);
            af[1] = f2tf(Ks[warp * 16 + g + 8][ks * 8 + t    ]);
            af[2] = f2tf(Ks[warp * 16 + g    ][ks * 8 + t + 4]);
            af[3] = f2tf(Ks[warp * 16 + g + 8][ks * 8 + t + 4]);
#pragma unroll
            for (int j = 0; j < 8; j++) {
                uint32_t bf[2];
                bf[0] = f2tf(Vs[ks * 8 + t    ][j * 8 + g]);
                bf[1] = f2tf(Vs[ks * 8 + t + 4][j * 8 + g]);
                mma_tf32(of[j], af, bf);
            }
        }
        __syncthreads();   // PV done before next tile's loads overwrite smem
    }

    // ---- finalize + store ----
    float inv0 = 1.0f / l0, inv1 = 1.0f / l1;
    int r0 = qrow0 + g, r1 = qrow0 + g + 8;
#pragma unroll
    for (int j = 0; j < 8; j++) {
        int c = h * D_HEAD + j * 8 + 2 * t;
        if (r0 < S_LEN)
            *(float2*)&out[(size_t)r0 * N_STATE + c] =
                make_float2(of[j][0] * inv0, of[j][1] * inv0);
        if (r1 < S_LEN)
            *(float2*)&out[(size_t)r1 * N_STATE + c] =
                make_float2(of[j][2] * inv1, of[j][3] * inv1);
    }
}

// ---------------------------------------------------------------------------
// Launch: 9 kernels on the default stream (graph-capturable, alloc-free)
// ---------------------------------------------------------------------------
extern "C" void kernel_launch(void* const* d_in, const int* in_sizes, int n_in,
                              void* d_out, int out_size) {
    (void)in_sizes; (void)n_in; (void)out_size;

    const float* x    = (const float*)d_in[0];
    const float* Wq   = (const float*)d_in[1];
    const float* bq   = (const float*)d_in[2];
    const float* Wk   = (const float*)d_in[3];
    const float* Wv   = (const float*)d_in[4];
    const float* bv   = (const float*)d_in[5];
    const float* Wo   = (const float*)d_in[6];
    const float* bo   = (const float*)d_in[7];
    const float* ln1g = (const float*)d_in[8];
    const float* ln1b = (const float*)d_in[9];
    const float* ln2g = (const float*)d_in[10];
    const float* ln2b = (const float*)d_in[11];
    const float* W1   = (const float*)d_in[12];
    const float* b1   = (const float*)d_in[13];
    const float* W2   = (const float*)d_in[14];
    const float* b2   = (const float*)d_in[15];
    float* out = (float*)d_out;

    Scratch* sc = nullptr;
    cudaGetSymbolAddress((void**)&sc, g_scratch);

    dim3 gQKV(N_STATE / G_BN, (S_LEN + G_BM - 1) / G_BM);   // (20, 12)
    dim3 gMLP1(N_MLP / G_BN, (S_LEN + G_BM - 1) / G_BM);    // (80, 12)

    // LN1
    ln_kernel<<<S_LEN, 256>>>(x, ln1g, ln1b, sc->h);
    // QKV projections
    gemm_tf32<<<gQKV, 256>>>(sc->h, Wq, bq,      nullptr, sc->q, S_LEN, N_STATE, N_STATE, 0);
    gemm_tf32<<<gQKV, 256>>>(sc->h, Wk, nullptr, nullptr, sc->k, S_LEN, N_STATE, N_STATE, 0);
    gemm_tf32<<<gQKV, 256>>>(sc->h, Wv, bv,      nullptr, sc->v, S_LEN, N_STATE, N_STATE, 0);
    // attention
    attn_kernel<<<dim3(NQT, N_HEAD), 128>>>(sc->q, sc->k, sc->v, sc->attn);
    // O-proj + residual
    gemm_tf32<<<gQKV, 256>>>(sc->attn, Wo, bo, x, sc->x1, S_LEN, N_STATE, N_STATE, 0);
    // LN2
    ln_kernel<<<S_LEN, 256>>>(sc->x1, ln2g, ln2b, sc->h);
    // MLP
    gemm_tf32<<<gMLP1, 256>>>(sc->h,  W1, b1, nullptr, sc->h2, S_LEN, N_MLP,  N_STATE, 1);
    gemm_tf32<<<gQKV, 256>>>(sc->h2, W2, b2, sc->x1,  out,    S_LEN, N_STATE, N_MLP,  0);
}

// round 4
// speedup vs baseline: 1.3219x; 1.3219x over previous
#include <cuda_runtime.h>
#include <cuda_bf16.h>
#include <cstdint>
#include <cstddef>

// ---------------------------------------------------------------------------
// Problem constants
// ---------------------------------------------------------------------------
#define S_LEN   1500
#define N_STATE 1280
#define N_HEAD  20
#define D_HEAD  64
#define N_MLP   5120
#define NQT     24          // ceil(1500/64) query/key tiles

// ---------------------------------------------------------------------------
// Scratch (static device memory; no allocations anywhere)
// ---------------------------------------------------------------------------
struct Scratch {
    float h   [S_LEN * N_STATE];   // LN output (reused for LN1 and LN2)
    float q   [S_LEN * N_STATE];
    float k   [S_LEN * N_STATE];
    float v   [S_LEN * N_STATE];
    float attn[S_LEN * N_STATE];   // attention output pre O-proj
    float x1  [S_LEN * N_STATE];   // after attention residual
    float h2  [S_LEN * N_MLP];     // MLP hidden
};
__device__ Scratch g_scratch;

// ---------------------------------------------------------------------------
// Helpers
// ---------------------------------------------------------------------------
__device__ __forceinline__ uint32_t f2tf(float x) {
    uint32_t r;
    asm("cvt.rna.tf32.f32 %0, %1;" : "=r"(r) : "f"(x));
    return r;
}

// D = A(16x8, tf32, row) * B(8x8, tf32, col) + C, fp32 accum. In-place on acc.
__device__ __forceinline__ void mma_tf32(float acc[4], const uint32_t a[4], const uint32_t b[2]) {
    asm volatile(
        "mma.sync.aligned.m16n8k8.row.col.f32.tf32.tf32.f32 "
        "{%0,%1,%2,%3}, {%4,%5,%6,%7}, {%8,%9}, {%0,%1,%2,%3};\n"
        : "+f"(acc[0]), "+f"(acc[1]), "+f"(acc[2]), "+f"(acc[3])
        : "r"(a[0]), "r"(a[1]), "r"(a[2]), "r"(a[3]),
          "r"(b[0]), "r"(b[1]));
}

__device__ __forceinline__ float gelu_exact(float x) {
    return 0.5f * x * (1.0f + erff(x * 0.7071067811865475f));
}

// ---------------------------------------------------------------------------
// LayerNorm: one block per row, 256 threads, C = 1280 = 5*256
// ---------------------------------------------------------------------------
__global__ void ln_kernel(const float* __restrict__ x,
                          const float* __restrict__ gamma,
                          const float* __restrict__ beta,
                          float* __restrict__ out) {
    int row = blockIdx.x;
    int tid = threadIdx.x;
    const float* xr = x + (size_t)row * N_STATE;
    float* orow = out + (size_t)row * N_STATE;

    __shared__ float red[256];
    float local[5];
    float s = 0.f;
#pragma unroll
    for (int i = 0; i < 5; i++) { local[i] = xr[tid + i * 256]; s += local[i]; }
    red[tid] = s; __syncthreads();
#pragma unroll
    for (int o = 128; o > 0; o >>= 1) {
        if (tid < o) red[tid] += red[tid + o];
        __syncthreads();
    }
    float mu = red[0] * (1.0f / N_STATE);
    __syncthreads();

    float vs = 0.f;
#pragma unroll
    for (int i = 0; i < 5; i++) { float d = local[i] - mu; vs += d * d; }
    red[tid] = vs; __syncthreads();
#pragma unroll
    for (int o = 128; o > 0; o >>= 1) {
        if (tid < o) red[tid] += red[tid + o];
        __syncthreads();
    }
    float inv = rsqrtf(red[0] * (1.0f / N_STATE) + 1e-5f);

#pragma unroll
    for (int i = 0; i < 5; i++) {
        int c = tid + i * 256;
        orow[c] = (local[i] - mu) * inv * gamma[c] + beta[c];
    }
}

// ---------------------------------------------------------------------------
// tf32 MMA GEMM, batched over blockIdx.z (shared A operand):
//   C_z[M,N] = act(A[M,K] @ B_z[K,N] + bias_z (+ res))
// BM=128, BN=64, BK=32, 256 threads = 8 warps (4x2), warp tile 32x32.
// smem holds PRE-CONVERTED tf32 bits (no cvt in the MMA loop), double-buffered,
// ONE __syncthreads per 32-deep k-slab.
//   As stride 36 words -> fragment banks (36g+t)%32 = (4g+t)%32 : conflict-free
//   Bs stride 72 words -> fragment banks (72t+g)%32 = (8t+g)%32 : conflict-free
// ---------------------------------------------------------------------------
#define G_BM 128
#define G_BN 64
#define G_BK 32
#define AS_STRIDE 36
#define BS_STRIDE 72
#define AS_BUF (G_BM * AS_STRIDE)           // 4608 words
#define BS_BUF (G_BK * BS_STRIDE)           // 2304 words
#define GEMM_SMEM_BYTES ((2 * AS_BUF + 2 * BS_BUF) * 4)   // 55296

struct GemmBatch {
    const float* B[3];
    const float* bias[3];
    float*       C[3];
};

__global__ __launch_bounds__(256, 2)
void gemm_tf32(const float* __restrict__ A, GemmBatch args,
               const float* __restrict__ res,
               int M, int N, int K, int act) {
    extern __shared__ uint32_t sm[];
    uint32_t* As = sm;                    // [2][128][36]
    uint32_t* Bs = sm + 2 * AS_BUF;       // [2][32][72]

    int z = blockIdx.z;
    const float* __restrict__ Bp   = args.B[z];
    const float* __restrict__ bias = args.bias[z];
    float* __restrict__       C    = args.C[z];

    int tid  = threadIdx.x;
    int warp = tid >> 5, lane = tid & 31;
    int g = lane >> 2, t = lane & 3;
    int wm = warp >> 1;       // 0..3 -> rows wm*32
    int wn = warp & 1;        // 0..1 -> cols wn*32
    int bm0 = blockIdx.y * G_BM;
    int bn0 = blockIdx.x * G_BN;

    // global load mapping
    int arow = tid >> 3;          // 0..31 (4 passes of 32 rows)
    int acol = (tid & 7) * 4;     // k offset within slab
    int brow = tid >> 4;          // 0..15 (2 passes of 16 rows)
    int bcol = (tid & 15) * 4;    // n offset

    float acc[2][4][4];
#pragma unroll
    for (int i = 0; i < 2; i++)
#pragma unroll
        for (int j = 0; j < 4; j++)
#pragma unroll
            for (int r = 0; r < 4; r++) acc[i][j][r] = 0.f;

    const float4 z4 = {0.f, 0.f, 0.f, 0.f};
    float4 pa[4], pb[2];

    auto loadg = [&](int k0) {
#pragma unroll
        for (int i = 0; i < 4; i++) {
            int r = bm0 + arow + 32 * i;
            pa[i] = (r < M) ? *(const float4*)&A[(size_t)r * K + k0 + acol] : z4;
        }
#pragma unroll
        for (int i = 0; i < 2; i++)
            pb[i] = *(const float4*)&Bp[(size_t)(k0 + brow + 16 * i) * N + bn0 + bcol];
    };
    auto stores = [&](int buf) {
        uint32_t* ab = As + buf * AS_BUF;
        uint32_t* bb = Bs + buf * BS_BUF;
#pragma unroll
        for (int i = 0; i < 4; i++) {
            uint32_t* p = ab + (arow + 32 * i) * AS_STRIDE + acol;
            p[0] = f2tf(pa[i].x); p[1] = f2tf(pa[i].y);
            p[2] = f2tf(pa[i].z); p[3] = f2tf(pa[i].w);
        }
#pragma unroll
        for (int i = 0; i < 2; i++) {
            uint32_t* p = bb + (brow + 16 * i) * BS_STRIDE + bcol;
            p[0] = f2tf(pb[i].x); p[1] = f2tf(pb[i].y);
            p[2] = f2tf(pb[i].z); p[3] = f2tf(pb[i].w);
        }
    };

    int nk = K / G_BK;
    loadg(0);
    stores(0);
    __syncthreads();

    for (int kt = 0; kt < nk; kt++) {
        int buf = kt & 1;
        if (kt + 1 < nk) loadg((kt + 1) * G_BK);

        const uint32_t* ab = As + buf * AS_BUF;
        const uint32_t* bb = Bs + buf * BS_BUF;
#pragma unroll
        for (int ks = 0; ks < 4; ks++) {
            uint32_t af[2][4], bf[4][2];
#pragma unroll
            for (int i = 0; i < 2; i++) {
                const uint32_t* base = ab + (wm * 32 + i * 16 + g) * AS_STRIDE + ks * 8 + t;
                af[i][0] = base[0];
                af[i][1] = base[8 * AS_STRIDE];
                af[i][2] = base[4];
                af[i][3] = base[8 * AS_STRIDE + 4];
            }
#pragma unroll
            for (int j = 0; j < 4; j++) {
                const uint32_t* base = bb + (ks * 8 + t) * BS_STRIDE + wn * 32 + j * 8 + g;
                bf[j][0] = base[0];
                bf[j][1] = base[4 * BS_STRIDE];
            }
#pragma unroll
            for (int i = 0; i < 2; i++)
#pragma unroll
                for (int j = 0; j < 4; j++)
                    mma_tf32(acc[i][j], af[i], bf[j]);
        }

        if (kt + 1 < nk) stores(buf ^ 1);
        __syncthreads();
    }

    // epilogue
#pragma unroll
    for (int i = 0; i < 2; i++) {
        int r0 = bm0 + wm * 32 + i * 16 + g;
        int r1 = r0 + 8;
#pragma unroll
        for (int j = 0; j < 4; j++) {
            int c = bn0 + wn * 32 + j * 8 + 2 * t;
            float bb0 = bias ? bias[c]     : 0.f;
            float bb1 = bias ? bias[c + 1] : 0.f;
            if (r0 < M) {
                float v0 = acc[i][j][0] + bb0, v1 = acc[i][j][1] + bb1;
                if (res) { v0 += res[(size_t)r0 * N + c]; v1 += res[(size_t)r0 * N + c + 1]; }
                if (act) { v0 = gelu_exact(v0); v1 = gelu_exact(v1); }
                *(float2*)&C[(size_t)r0 * N + c] = make_float2(v0, v1);
            }
            if (r1 < M) {
                float v2 = acc[i][j][2] + bb0, v3 = acc[i][j][3] + bb1;
                if (res) { v2 += res[(size_t)r1 * N + c]; v3 += res[(size_t)r1 * N + c + 1]; }
                if (act) { v2 = gelu_exact(v2); v3 = gelu_exact(v3); }
                *(float2*)&C[(size_t)r1 * N + c] = make_float2(v2, v3);
            }
        }
    }
}

// ---------------------------------------------------------------------------
// Fused flash attention (non-causal). Block = (q-tile of 64, head). 128 thr.
// Warp w owns query rows qt*64 + w*16 .. +15. Q fragments in registers
// (pre-scaled by D_HEAD^-0.5 = 0.125). Online softmax in fp32.
// K/V/P staged in smem as PRE-CONVERTED tf32 bits (no cvt in the MMA loops).
//   Ks stride 68: QK B-frag banks (g*68+t)%32 = (4g+t)%32 -> conflict-free
//                 PV A-frag banks  same pattern           -> conflict-free
//   Vs stride 72: PV B-frag banks (t*72+g)%32 = (8t+g)%32 -> conflict-free
// ---------------------------------------------------------------------------
__global__ __launch_bounds__(128)
void attn_kernel(const float* __restrict__ qp, const float* __restrict__ kp,
                 const float* __restrict__ vp, float* __restrict__ out) {
    __shared__ uint32_t Ks[64][68];   // K tile (tf32 bits), then P
    __shared__ uint32_t Vs[64][72];

    int qt = blockIdx.x;
    int h  = blockIdx.y;
    int tid = threadIdx.x, warp = tid >> 5, lane = tid & 31;
    int g = lane >> 2, t = lane & 3;
    int qrow0 = qt * 64 + warp * 16;
    const float scale = 0.125f;   // 64^-0.5

    // ---- preload Q fragments (8 k-steps over D_HEAD=64) ----
    uint32_t qf[8][4];
    {
        int rA = qrow0 + g, rB = qrow0 + g + 8;
        bool okA = rA < S_LEN, okB = rB < S_LEN;
        const float* qA = qp + (size_t)rA * N_STATE + h * D_HEAD;
        const float* qB = qp + (size_t)rB * N_STATE + h * D_HEAD;
#pragma unroll
        for (int ks = 0; ks < 8; ks++) {
            float a0 = okA ? qA[ks * 8 + t]     : 0.f;
            float a1 = okB ? qB[ks * 8 + t]     : 0.f;
            float a2 = okA ? qA[ks * 8 + t + 4] : 0.f;
            float a3 = okB ? qB[ks * 8 + t + 4] : 0.f;
            qf[ks][0] = f2tf(a0 * scale);
            qf[ks][1] = f2tf(a1 * scale);
            qf[ks][2] = f2tf(a2 * scale);
            qf[ks][3] = f2tf(a3 * scale);
        }
    }

    float of[8][4];
#pragma unroll
    for (int j = 0; j < 8; j++)
#pragma unroll
        for (int r = 0; r < 4; r++) of[j][r] = 0.f;
    float m0 = -1e30f, m1 = -1e30f, l0 = 0.f, l1 = 0.f;

    const float4 z4 = {0.f, 0.f, 0.f, 0.f};

    for (int kt = 0; kt < NQT; kt++) {
        // ---- load K,V tile (64 keys x 64 dims), convert to tf32 at store ----
#pragma unroll
        for (int rep = 0; rep < 8; rep++) {
            int idx = rep * 128 + tid;
            int row = idx >> 4;
            int q4  = (idx & 15) * 4;
            int gkey = kt * 64 + row;
            float4 kv = z4, vv = z4;
            if (gkey < S_LEN) {
                kv = *(const float4*)&kp[(size_t)gkey * N_STATE + h * D_HEAD + q4];
                vv = *(const float4*)&vp[(size_t)gkey * N_STATE + h * D_HEAD + q4];
            }
            uint4 kb = {f2tf(kv.x), f2tf(kv.y), f2tf(kv.z), f2tf(kv.w)};
            uint4 vb = {f2tf(vv.x), f2tf(vv.y), f2tf(vv.z), f2tf(vv.w)};
            *(uint4*)&Ks[row][q4] = kb;
            *(uint4*)&Vs[row][q4] = vb;
        }
        __syncthreads();

        // ---- S = Q * K^T  (16 x 64 per warp) ----
        float sacc[8][4];
#pragma unroll
        for (int j = 0; j < 8; j++)
#pragma unroll
            for (int r = 0; r < 4; r++) sacc[j][r] = 0.f;

#pragma unroll
        for (int ks = 0; ks < 8; ks++) {
#pragma unroll
            for (int j = 0; j < 8; j++) {
                uint32_t bf[2];
                bf[0] = Ks[j * 8 + g][ks * 8 + t    ];
                bf[1] = Ks[j * 8 + g][ks * 8 + t + 4];
                mma_tf32(sacc[j], qf[ks], bf);
            }
        }

        // ---- mask padded keys (only last tile) ----
        if (kt == NQT - 1) {
#pragma unroll
            for (int j = 0; j < 8; j++) {
                int c = j * 8 + 2 * t;
                if (1472 + c     >= S_LEN) { sacc[j][0] = -1e30f; sacc[j][2] = -1e30f; }
                if (1472 + c + 1 >= S_LEN) { sacc[j][1] = -1e30f; sacc[j][3] = -1e30f; }
            }
        }

        // ---- online softmax ----
        float tm0 = -1e30f, tm1 = -1e30f;
#pragma unroll
        for (int j = 0; j < 8; j++) {
            tm0 = fmaxf(tm0, fmaxf(sacc[j][0], sacc[j][1]));
            tm1 = fmaxf(tm1, fmaxf(sacc[j][2], sacc[j][3]));
        }
        tm0 = fmaxf(tm0, __shfl_xor_sync(0xffffffffu, tm0, 1));
        tm0 = fmaxf(tm0, __shfl_xor_sync(0xffffffffu, tm0, 2));
        tm1 = fmaxf(tm1, __shfl_xor_sync(0xffffffffu, tm1, 1));
        tm1 = fmaxf(tm1, __shfl_xor_sync(0xffffffffu, tm1, 2));

        float nm0 = fmaxf(m0, tm0), nm1 = fmaxf(m1, tm1);
        float c0 = __expf(m0 - nm0), c1 = __expf(m1 - nm1);
        l0 *= c0; l1 *= c1;
#pragma unroll
        for (int j = 0; j < 8; j++) {
            of[j][0] *= c0; of[j][1] *= c0;
            of[j][2] *= c1; of[j][3] *= c1;
        }
        m0 = nm0; m1 = nm1;

        // wait for ALL warps to finish reading Ks before overwriting with P
        __syncthreads();

        float ps0 = 0.f, ps1 = 0.f;
#pragma unroll
        for (int j = 0; j < 8; j++) {
            float p0 = __expf(sacc[j][0] - nm0);
            float p1 = __expf(sacc[j][1] - nm0);
            float p2 = __expf(sacc[j][2] - nm1);
            float p3 = __expf(sacc[j][3] - nm1);
            ps0 += p0 + p1; ps1 += p2 + p3;
            int c = j * 8 + 2 * t;
            uint2 pa = {f2tf(p0), f2tf(p1)};
            uint2 pc = {f2tf(p2), f2tf(p3)};
            *(uint2*)&Ks[warp * 16 + g    ][c] = pa;
            *(uint2*)&Ks[warp * 16 + g + 8][c] = pc;
        }
        ps0 += __shfl_xor_sync(0xffffffffu, ps0, 1);
        ps0 += __shfl_xor_sync(0xffffffffu, ps0, 2);
        ps1 += __shfl_xor_sync(0xffffffffu, ps1, 1);
        ps1 += __shfl_xor_sync(0xffffffffu, ps1, 2);
        l0 += ps0; l1 += ps1;
        __syncwarp();

        // ---- O += P * V ----
#pragma unroll
        for (int ks = 0; ks < 8; ks++) {
            uint32_t af[4];
            af[0] = Ks[warp * 16 + g    ][ks * 8 + t    ];
            af[1] = Ks[warp * 16 + g + 8][ks * 8 + t    ];
            af[2] = Ks[warp * 16 + g    ][ks * 8 + t + 4];
            af[3] = Ks[warp * 16 + g + 8][ks * 8 + t + 4];
#pragma unroll
            for (int j = 0; j < 8; j++) {
                uint32_t bf[2];
                bf[0] = Vs[ks * 8 + t    ][j * 8 + g];
                bf[1] = Vs[ks * 8 + t + 4][j * 8 + g];
                mma_tf32(of[j], af, bf);
            }
        }
        __syncthreads();   // PV done before next tile's loads overwrite smem
    }

    // ---- finalize + store ----
    float inv0 = 1.0f / l0, inv1 = 1.0f / l1;
    int r0 = qrow0 + g, r1 = qrow0 + g + 8;
#pragma unroll
    for (int j = 0; j < 8; j++) {
        int c = h * D_HEAD + j * 8 + 2 * t;
        if (r0 < S_LEN)
            *(float2*)&out[(size_t)r0 * N_STATE + c] =
                make_float2(of[j][0] * inv0, of[j][1] * inv0);
        if (r1 < S_LEN)
            *(float2*)&out[(size_t)r1 * N_STATE + c] =
                make_float2(of[j][2] * inv1, of[j][3] * inv1);
    }
}

// ---------------------------------------------------------------------------
// Launch: 7 kernels on the default stream (graph-capturable, alloc-free)
// ---------------------------------------------------------------------------
extern "C" void kernel_launch(void* const* d_in, const int* in_sizes, int n_in,
                              void* d_out, int out_size) {
    (void)in_sizes; (void)n_in; (void)out_size;

    const float* x    = (const float*)d_in[0];
    const float* Wq   = (const float*)d_in[1];
    const float* bq   = (const float*)d_in[2];
    const float* Wk   = (const float*)d_in[3];
    const float* Wv   = (const float*)d_in[4];
    const float* bv   = (const float*)d_in[5];
    const float* Wo   = (const float*)d_in[6];
    const float* bo   = (const float*)d_in[7];
    const float* ln1g = (const float*)d_in[8];
    const float* ln1b = (const float*)d_in[9];
    const float* ln2g = (const float*)d_in[10];
    const float* ln2b = (const float*)d_in[11];
    const float* W1   = (const float*)d_in[12];
    const float* b1   = (const float*)d_in[13];
    const float* W2   = (const float*)d_in[14];
    const float* b2   = (const float*)d_in[15];
    float* out = (float*)d_out;

    Scratch* sc = nullptr;
    cudaGetSymbolAddress((void**)&sc, g_scratch);

    cudaFuncSetAttribute(gemm_tf32,
                         cudaFuncAttributeMaxDynamicSharedMemorySize,
                         GEMM_SMEM_BYTES);

    dim3 gQKV(N_STATE / G_BN, (S_LEN + G_BM - 1) / G_BM, 3);   // (20, 12, 3)
    dim3 gOne(N_STATE / G_BN, (S_LEN + G_BM - 1) / G_BM, 1);   // (20, 12, 1)
    dim3 gMLP1(N_MLP / G_BN, (S_LEN + G_BM - 1) / G_BM, 1);    // (80, 12, 1)

    // LN1
    ln_kernel<<<S_LEN, 256>>>(x, ln1g, ln1b, sc->h);

    // QKV projections (one fused launch, shared A)
    GemmBatch qkv;
    qkv.B[0] = Wq; qkv.bias[0] = bq;      qkv.C[0] = sc->q;
    qkv.B[1] = Wk; qkv.bias[1] = nullptr; qkv.C[1] = sc->k;
    qkv.B[2] = Wv; qkv.bias[2] = bv;      qkv.C[2] = sc->v;
    gemm_tf32<<<gQKV, 256, GEMM_SMEM_BYTES>>>(sc->h, qkv, nullptr,
                                              S_LEN, N_STATE, N_STATE, 0);

    // attention
    attn_kernel<<<dim3(NQT, N_HEAD), 128>>>(sc->q, sc->k, sc->v, sc->attn);

    // O-proj + residual
    GemmBatch oproj;
    oproj.B[0] = Wo; oproj.bias[0] = bo; oproj.C[0] = sc->x1;
    oproj.B[1] = oproj.B[2] = nullptr; oproj.bias[1] = oproj.bias[2] = nullptr;
    oproj.C[1] = oproj.C[2] = nullptr;
    gemm_tf32<<<gOne, 256, GEMM_SMEM_BYTES>>>(sc->attn, oproj, x,
                                              S_LEN, N_STATE, N_STATE, 0);

    // LN2
    ln_kernel<<<S_LEN, 256>>>(sc->x1, ln2g, ln2b, sc->h);

    // MLP1 (+exact GELU)
    GemmBatch m1;
    m1.B[0] = W1; m1.bias[0] = b1; m1.C[0] = sc->h2;
    m1.B[1] = m1.B[2] = nullptr; m1.bias[1] = m1.bias[2] = nullptr;
    m1.C[1] = m1.C[2] = nullptr;
    gemm_tf32<<<gMLP1, 256, GEMM_SMEM_BYTES>>>(sc->h, m1, nullptr,
                                               S_LEN, N_MLP, N_STATE, 1);

    // MLP2 (+residual) -> d_out
    GemmBatch m2;
    m2.B[0] = W2; m2.bias[0] = b2; m2.C[0] = out;
    m2.B[1] = m2.B[2] = nullptr; m2.bias[1] = m2.bias[2] = nullptr;
    m2.C[1] = m2.C[2] = nullptr;
    gemm_tf32<<<gOne, 256, GEMM_SMEM_BYTES>>>(sc->h2, m2, sc->x1,
                                              S_LEN, N_STATE, N_MLP, 0);
}

// round 6
// speedup vs baseline: 1.6661x; 1.2604x over previous
#include <cuda_runtime.h>
#include <cuda_bf16.h>
#include <cstdint>
#include <cstddef>

// ---------------------------------------------------------------------------
// Problem constants
// ---------------------------------------------------------------------------
#define S_LEN   1500
#define N_STATE 1280
#define N_HEAD  20
#define D_HEAD  64
#define N_MLP   5120
#define NKT     24          // key tiles of 64

// ---------------------------------------------------------------------------
// Scratch (static device memory; no allocations anywhere)
// ---------------------------------------------------------------------------
struct Scratch {
    float h   [S_LEN * N_STATE];
    float q   [S_LEN * N_STATE];
    float k   [S_LEN * N_STATE];
    float v   [S_LEN * N_STATE];
    float attn[S_LEN * N_STATE];
    float x1  [S_LEN * N_STATE];
    float h2  [S_LEN * N_MLP];
};
__device__ Scratch g_scratch;

// ---------------------------------------------------------------------------
// Helpers
// ---------------------------------------------------------------------------
// Raw fp32 bits are valid tf32 MMA operands (HW truncates the low mantissa).
__device__ __forceinline__ void mma_tf32(float acc[4], const uint32_t a[4], const uint32_t b[2]) {
    asm volatile(
        "mma.sync.aligned.m16n8k8.row.col.f32.tf32.tf32.f32 "
        "{%0,%1,%2,%3}, {%4,%5,%6,%7}, {%8,%9}, {%0,%1,%2,%3};\n"
        : "+f"(acc[0]), "+f"(acc[1]), "+f"(acc[2]), "+f"(acc[3])
        : "r"(a[0]), "r"(a[1]), "r"(a[2]), "r"(a[3]),
          "r"(b[0]), "r"(b[1]));
}

__device__ __forceinline__ void cp16(uint32_t dst, const float* src, bool ok) {
    int n = ok ? 16 : 0;   // zfill when out of range
    asm volatile("cp.async.cg.shared.global [%0], [%1], 16, %2;\n"
                 :: "r"(dst), "l"(src), "r"(n));
}
#define CP_COMMIT() asm volatile("cp.async.commit_group;\n")
#define CP_WAIT(N)  asm volatile("cp.async.wait_group %0;\n" :: "n"(N))

__device__ __forceinline__ float gelu_exact(float x) {
    return 0.5f * x * (1.0f + erff(x * 0.7071067811865475f));
}

// ---------------------------------------------------------------------------
// LayerNorm: one block per row, 256 threads, C = 1280 = 5*256
// ---------------------------------------------------------------------------
__global__ void ln_kernel(const float* __restrict__ x,
                          const float* __restrict__ gamma,
                          const float* __restrict__ beta,
                          float* __restrict__ out) {
    int row = blockIdx.x;
    int tid = threadIdx.x;
    const float* xr = x + (size_t)row * N_STATE;
    float* orow = out + (size_t)row * N_STATE;

    __shared__ float red[256];
    float local[5];
    float s = 0.f;
#pragma unroll
    for (int i = 0; i < 5; i++) { local[i] = xr[tid + i * 256]; s += local[i]; }
    red[tid] = s; __syncthreads();
#pragma unroll
    for (int o = 128; o > 0; o >>= 1) {
        if (tid < o) red[tid] += red[tid + o];
        __syncthreads();
    }
    float mu = red[0] * (1.0f / N_STATE);
    __syncthreads();

    float vs = 0.f;
#pragma unroll
    for (int i = 0; i < 5; i++) { float d = local[i] - mu; vs += d * d; }
    red[tid] = vs; __syncthreads();
#pragma unroll
    for (int o = 128; o > 0; o >>= 1) {
        if (tid < o) red[tid] += red[tid + o];
        __syncthreads();
    }
    float inv = rsqrtf(red[0] * (1.0f / N_STATE) + 1e-5f);

#pragma unroll
    for (int i = 0; i < 5; i++) {
        int c = tid + i * 256;
        orow[c] = (local[i] - mu) * inv * gamma[c] + beta[c];
    }
}

// ---------------------------------------------------------------------------
// tf32 MMA GEMM, batched over blockIdx.z (shared A operand):
//   C_z[M,N] = act(A[M,K] @ B_z[K,N] + bias_z (+ res))
// BM=128, BN=128, BK=32; 256 threads = 8 warps (2 m x 4 n), warp tile 64x32.
// cp.async double-buffered smem of RAW fp32 bits; LDS/MMA = 1.5.
//   As stride 36: frag banks (36g+t)%32 = (4g+t)  -> conflict-free
//   Bs stride 136: frag banks (136t+g)%32 = (8t+g) -> conflict-free
// ---------------------------------------------------------------------------
#define G_BM 128
#define G_BN 128
#define G_BK 32
#define AS_STRIDE 36
#define BS_STRIDE 136
#define AS_BUF (G_BM * AS_STRIDE)                      // 4608 words
#define BS_BUF (G_BK * BS_STRIDE)                      // 4352 words
#define GEMM_SMEM_BYTES ((2 * AS_BUF + 2 * BS_BUF) * 4)   // 71680

struct GemmBatch {
    const float* B[3];
    const float* bias[3];
    float*       C[3];
};

__global__ __launch_bounds__(256, 2)
void gemm_tf32(const float* __restrict__ A, GemmBatch args,
               const float* __restrict__ res,
               int M, int N, int K, int act) {
    extern __shared__ uint32_t sm[];

    int z = blockIdx.z;
    const float* __restrict__ Bp   = args.B[z];
    const float* __restrict__ bias = args.bias[z];
    float* __restrict__       C    = args.C[z];

    int tid  = threadIdx.x;
    int warp = tid >> 5, lane = tid & 31;
    int g = lane >> 2, t = lane & 3;
    int wm = warp >> 2;       // 0..1 -> rows wm*64
    int wn = warp & 3;        // 0..3 -> cols wn*32
    int bm0 = blockIdx.y * G_BM;
    int bn0 = blockIdx.x * G_BN;

    uint32_t sbase = (uint32_t)__cvta_generic_to_shared(sm);

    // cp.async mappings
    int arow = tid >> 3;          // 0..31 (+32*i)
    int acol = (tid & 7) * 4;     // k offset
    int brow = tid >> 5;          // 0..7  (+8*i)
    int bcol = (tid & 31) * 4;    // n offset

    const float* aptr = A + (size_t)(bm0 + arow) * K + acol;
    const float* bptr = Bp + (size_t)brow * N + bn0 + bcol;

    auto loadg = [&](int k0, int buf) {
        uint32_t ad = sbase + (buf * AS_BUF) * 4;
#pragma unroll
        for (int i = 0; i < 4; i++) {
            int r = bm0 + arow + 32 * i;
            cp16(ad + ((arow + 32 * i) * AS_STRIDE + acol) * 4,
                 aptr + (size_t)(32 * i) * K + k0, r < M);
        }
        uint32_t bd = sbase + (2 * AS_BUF + buf * BS_BUF) * 4;
#pragma unroll
        for (int i = 0; i < 4; i++) {
            cp16(bd + ((brow + 8 * i) * BS_STRIDE + bcol) * 4,
                 bptr + (size_t)(k0 + 8 * i) * N, true);
        }
        CP_COMMIT();
    };

    float acc[4][4][4];
#pragma unroll
    for (int i = 0; i < 4; i++)
#pragma unroll
        for (int j = 0; j < 4; j++)
#pragma unroll
            for (int r = 0; r < 4; r++) acc[i][j][r] = 0.f;

    int nk = K / G_BK;
    loadg(0, 0);

    for (int kt = 0; kt < nk; kt++) {
        int buf = kt & 1;
        if (kt + 1 < nk) { loadg((kt + 1) * G_BK, buf ^ 1); CP_WAIT(1); }
        else             { CP_WAIT(0); }
        __syncthreads();

        const uint32_t* ab = sm + buf * AS_BUF;
        const uint32_t* bb = sm + 2 * AS_BUF + buf * BS_BUF;
#pragma unroll
        for (int ks = 0; ks < 4; ks++) {
            uint32_t af[4][4], bf[4][2];
#pragma unroll
            for (int i = 0; i < 4; i++) {
                const uint32_t* base = ab + (wm * 64 + i * 16 + g) * AS_STRIDE + ks * 8 + t;
                af[i][0] = base[0];
                af[i][1] = base[8 * AS_STRIDE];
                af[i][2] = base[4];
                af[i][3] = base[8 * AS_STRIDE + 4];
            }
#pragma unroll
            for (int j = 0; j < 4; j++) {
                const uint32_t* base = bb + (ks * 8 + t) * BS_STRIDE + wn * 32 + j * 8 + g;
                bf[j][0] = base[0];
                bf[j][1] = base[4 * BS_STRIDE];
            }
#pragma unroll
            for (int i = 0; i < 4; i++)
#pragma unroll
                for (int j = 0; j < 4; j++)
                    mma_tf32(acc[i][j], af[i], bf[j]);
        }
        __syncthreads();   // before next slab's cp.async overwrites this buffer
    }

    // epilogue
#pragma unroll
    for (int i = 0; i < 4; i++) {
        int r0 = bm0 + wm * 64 + i * 16 + g;
        int r1 = r0 + 8;
#pragma unroll
        for (int j = 0; j < 4; j++) {
            int c = bn0 + wn * 32 + j * 8 + 2 * t;
            float bb0 = bias ? bias[c]     : 0.f;
            float bb1 = bias ? bias[c + 1] : 0.f;
            if (r0 < M) {
                float v0 = acc[i][j][0] + bb0, v1 = acc[i][j][1] + bb1;
                if (res) { v0 += res[(size_t)r0 * N + c]; v1 += res[(size_t)r0 * N + c + 1]; }
                if (act) { v0 = gelu_exact(v0); v1 = gelu_exact(v1); }
                *(float2*)&C[(size_t)r0 * N + c] = make_float2(v0, v1);
            }
            if (r1 < M) {
                float v2 = acc[i][j][2] + bb0, v3 = acc[i][j][3] + bb1;
                if (res) { v2 += res[(size_t)r1 * N + c]; v3 += res[(size_t)r1 * N + c + 1]; }
                if (act) { v2 = gelu_exact(v2); v3 = gelu_exact(v3); }
                *(float2*)&C[(size_t)r1 * N + c] = make_float2(v2, v3);
            }
        }
    }
}

// ---------------------------------------------------------------------------
// Fused flash attention (non-causal).
// Block = (q-tile of 128, head), 256 threads = 8 warps, warp owns 16 q rows.
// K-tile = 64 keys. Q frags in registers (pre-scaled). smem holds RAW fp32
// bits. P staged into the Ks region rows 0..127 (K occupies rows 0..63).
//   Ks stride 68: banks (4g+t) conflict-free; Vs stride 72: (8t+g) free.
// smem = 128*68 + 64*72 words = 53248 B -> 2 CTAs/SM, grid 240 = 1 wave.
// ---------------------------------------------------------------------------
#define KS_STRIDE 68
#define VS_STRIDE 72
#define KS_WORDS (128 * KS_STRIDE)
#define ATTN_SMEM_BYTES ((KS_WORDS + 64 * VS_STRIDE) * 4)   // 53248

__global__ __launch_bounds__(256, 2)
void attn_kernel(const float* __restrict__ qp, const float* __restrict__ kp,
                 const float* __restrict__ vp, float* __restrict__ out) {
    extern __shared__ uint32_t smn[];
    uint32_t* Ks = smn;                 // [128][68] (K in rows 0..63, then P)
    uint32_t* Vs = smn + KS_WORDS;      // [64][72]

    int qt = blockIdx.x;
    int h  = blockIdx.y;
    int tid = threadIdx.x, warp = tid >> 5, lane = tid & 31;
    int g = lane >> 2, t = lane & 3;
    int qrow0 = qt * 128 + warp * 16;
    uint32_t sbase = (uint32_t)__cvta_generic_to_shared(smn);

    // ---- preload Q fragments (raw bits, pre-scaled by 64^-0.5) ----
    uint32_t qf[8][4];
    {
        int rA = qrow0 + g, rB = qrow0 + g + 8;
        bool okA = rA < S_LEN, okB = rB < S_LEN;
        const float* qA = qp + (size_t)rA * N_STATE + h * D_HEAD;
        const float* qB = qp + (size_t)rB * N_STATE + h * D_HEAD;
#pragma unroll
        for (int ks = 0; ks < 8; ks++) {
            float a0 = okA ? qA[ks * 8 + t]     : 0.f;
            float a1 = okB ? qB[ks * 8 + t]     : 0.f;
            float a2 = okA ? qA[ks * 8 + t + 4] : 0.f;
            float a3 = okB ? qB[ks * 8 + t + 4] : 0.f;
            qf[ks][0] = __float_as_uint(a0 * 0.125f);
            qf[ks][1] = __float_as_uint(a1 * 0.125f);
            qf[ks][2] = __float_as_uint(a2 * 0.125f);
            qf[ks][3] = __float_as_uint(a3 * 0.125f);
        }
    }

    float of[8][4];
#pragma unroll
    for (int j = 0; j < 8; j++)
#pragma unroll
        for (int r = 0; r < 4; r++) of[j][r] = 0.f;
    float m0 = -1e30f, m1 = -1e30f, l0 = 0.f, l1 = 0.f;

    int lrow = tid >> 4;            // 0..15
    int lc4  = (tid & 15) * 4;      // 0..60
    const float* kpb = kp + h * D_HEAD + lc4;
    const float* vpb = vp + h * D_HEAD + lc4;

    for (int kt = 0; kt < NKT; kt++) {
        // ---- cp.async K,V tile (64 keys x 64 dims), zfill past S_LEN ----
#pragma unroll
        for (int p = 0; p < 4; p++) {
            int row = lrow + p * 16;
            int gk = kt * 64 + row;
            cp16(sbase + (row * KS_STRIDE + lc4) * 4,
                 kpb + (size_t)gk * N_STATE, gk < S_LEN);
        }
#pragma unroll
        for (int p = 0; p < 4; p++) {
            int row = lrow + p * 16;
            int gk = kt * 64 + row;
            cp16(sbase + (KS_WORDS + row * VS_STRIDE + lc4) * 4,
                 vpb + (size_t)gk * N_STATE, gk < S_LEN);
        }
        CP_COMMIT();
        CP_WAIT(0);
        __syncthreads();

        // ---- S = Q * K^T  (16 x 64 per warp) ----
        float sacc[8][4];
#pragma unroll
        for (int j = 0; j < 8; j++)
#pragma unroll
            for (int r = 0; r < 4; r++) sacc[j][r] = 0.f;

#pragma unroll
        for (int ks = 0; ks < 8; ks++) {
#pragma unroll
            for (int j = 0; j < 8; j++) {
                uint32_t bf[2];
                const uint32_t* base = Ks + (j * 8 + g) * KS_STRIDE + ks * 8 + t;
                bf[0] = base[0];
                bf[1] = base[4];
                mma_tf32(sacc[j], qf[ks], bf);
            }
        }

        // ---- mask padded keys (only last tile) ----
        if (kt == NKT - 1) {
#pragma unroll
            for (int j = 0; j < 8; j++) {
                int c = j * 8 + 2 * t;
                if (1472 + c     >= S_LEN) { sacc[j][0] = -1e30f; sacc[j][2] = -1e30f; }
                if (1472 + c + 1 >= S_LEN) { sacc[j][1] = -1e30f; sacc[j][3] = -1e30f; }
            }
        }

        // ---- online softmax ----
        float tm0 = -1e30f, tm1 = -1e30f;
#pragma unroll
        for (int j = 0; j < 8; j++) {
            tm0 = fmaxf(tm0, fmaxf(sacc[j][0], sacc[j][1]));
            tm1 = fmaxf(tm1, fmaxf(sacc[j][2], sacc[j][3]));
        }
        tm0 = fmaxf(tm0, __shfl_xor_sync(0xffffffffu, tm0, 1));
        tm0 = fmaxf(tm0, __shfl_xor_sync(0xffffffffu, tm0, 2));
        tm1 = fmaxf(tm1, __shfl_xor_sync(0xffffffffu, tm1, 1));
        tm1 = fmaxf(tm1, __shfl_xor_sync(0xffffffffu, tm1, 2));

        float nm0 = fmaxf(m0, tm0), nm1 = fmaxf(m1, tm1);
        float c0 = __expf(m0 - nm0), c1 = __expf(m1 - nm1);
        l0 *= c0; l1 *= c1;
#pragma unroll
        for (int j = 0; j < 8; j++) {
            of[j][0] *= c0; of[j][1] *= c0;
            of[j][2] *= c1; of[j][3] *= c1;
        }
        m0 = nm0; m1 = nm1;

        // all warps must be done reading K before P overwrites rows 0..63
        __syncthreads();

        float ps0 = 0.f, ps1 = 0.f;
#pragma unroll
        for (int j = 0; j < 8; j++) {
            float p0 = __expf(sacc[j][0] - nm0);
            float p1 = __expf(sacc[j][1] - nm0);
            float p2 = __expf(sacc[j][2] - nm1);
            float p3 = __expf(sacc[j][3] - nm1);
            ps0 += p0 + p1; ps1 += p2 + p3;
            int c = j * 8 + 2 * t;
            uint2 pa = {__float_as_uint(p0), __float_as_uint(p1)};
            uint2 pc = {__float_as_uint(p2), __float_as_uint(p3)};
            *(uint2*)&Ks[(warp * 16 + g)     * KS_STRIDE + c] = pa;
            *(uint2*)&Ks[(warp * 16 + g + 8) * KS_STRIDE + c] = pc;
        }
        ps0 += __shfl_xor_sync(0xffffffffu, ps0, 1);
        ps0 += __shfl_xor_sync(0xffffffffu, ps0, 2);
        ps1 += __shfl_xor_sync(0xffffffffu, ps1, 1);
        ps1 += __shfl_xor_sync(0xffffffffu, ps1, 2);
        l0 += ps0; l1 += ps1;
        __syncwarp();

        // ---- O += P * V (warp reads only its own P rows) ----
#pragma unroll
        for (int ks = 0; ks < 8; ks++) {
            uint32_t af[4];
            const uint32_t* pb = Ks + (warp * 16 + g) * KS_STRIDE + ks * 8 + t;
            af[0] = pb[0];
            af[1] = pb[8 * KS_STRIDE];
            af[2] = pb[4];
            af[3] = pb[8 * KS_STRIDE + 4];
#pragma unroll
            for (int j = 0; j < 8; j++) {
                uint32_t bf[2];
                const uint32_t* vb = Vs + (ks * 8 + t) * VS_STRIDE + j * 8 + g;
                bf[0] = vb[0];
                bf[1] = vb[4 * VS_STRIDE];
                mma_tf32(of[j], af, bf);
            }
        }
        __syncthreads();   // PV done before next tile's loads overwrite smem
    }

    // ---- finalize + store ----
    float inv0 = 1.0f / l0, inv1 = 1.0f / l1;
    int r0 = qrow0 + g, r1 = qrow0 + g + 8;
#pragma unroll
    for (int j = 0; j < 8; j++) {
        int c = h * D_HEAD + j * 8 + 2 * t;
        if (r0 < S_LEN)
            *(float2*)&out[(size_t)r0 * N_STATE + c] =
                make_float2(of[j][0] * inv0, of[j][1] * inv0);
        if (r1 < S_LEN)
            *(float2*)&out[(size_t)r1 * N_STATE + c] =
                make_float2(of[j][2] * inv1, of[j][3] * inv1);
    }
}

// ---------------------------------------------------------------------------
// Launch: 7 kernels on the default stream (graph-capturable, alloc-free)
// ---------------------------------------------------------------------------
extern "C" void kernel_launch(void* const* d_in, const int* in_sizes, int n_in,
                              void* d_out, int out_size) {
    (void)in_sizes; (void)n_in; (void)out_size;

    const float* x    = (const float*)d_in[0];
    const float* Wq   = (const float*)d_in[1];
    const float* bq   = (const float*)d_in[2];
    const float* Wk   = (const float*)d_in[3];
    const float* Wv   = (const float*)d_in[4];
    const float* bv   = (const float*)d_in[5];
    const float* Wo   = (const float*)d_in[6];
    const float* bo   = (const float*)d_in[7];
    const float* ln1g = (const float*)d_in[8];
    const float* ln1b = (const float*)d_in[9];
    const float* ln2g = (const float*)d_in[10];
    const float* ln2b = (const float*)d_in[11];
    const float* W1   = (const float*)d_in[12];
    const float* b1   = (const float*)d_in[13];
    const float* W2   = (const float*)d_in[14];
    const float* b2   = (const float*)d_in[15];
    float* out = (float*)d_out;

    Scratch* sc = nullptr;
    cudaGetSymbolAddress((void**)&sc, g_scratch);

    cudaFuncSetAttribute(gemm_tf32,
                         cudaFuncAttributeMaxDynamicSharedMemorySize,
                         GEMM_SMEM_BYTES);
    cudaFuncSetAttribute(attn_kernel,
                         cudaFuncAttributeMaxDynamicSharedMemorySize,
                         ATTN_SMEM_BYTES);

    dim3 gQKV(N_STATE / G_BN, (S_LEN + G_BM - 1) / G_BM, 3);   // (10, 12, 3)
    dim3 gOne(N_STATE / G_BN, (S_LEN + G_BM - 1) / G_BM, 1);   // (10, 12, 1)
    dim3 gMLP1(N_MLP / G_BN, (S_LEN + G_BM - 1) / G_BM, 1);    // (40, 12, 1)

    // LN1
    ln_kernel<<<S_LEN, 256>>>(x, ln1g, ln1b, sc->h);

    // QKV projections (one fused launch, shared A)
    GemmBatch qkv;
    qkv.B[0] = Wq; qkv.bias[0] = bq;      qkv.C[0] = sc->q;
    qkv.B[1] = Wk; qkv.bias[1] = nullptr; qkv.C[1] = sc->k;
    qkv.B[2] = Wv; qkv.bias[2] = bv;      qkv.C[2] = sc->v;
    gemm_tf32<<<gQKV, 256, GEMM_SMEM_BYTES>>>(sc->h, qkv, nullptr,
                                              S_LEN, N_STATE, N_STATE, 0);

    // attention: grid (q-tiles of 128, heads)
    attn_kernel<<<dim3(12, N_HEAD), 256, ATTN_SMEM_BYTES>>>(sc->q, sc->k, sc->v, sc->attn);

    // O-proj + residual
    GemmBatch oproj;
    oproj.B[0] = Wo; oproj.bias[0] = bo; oproj.C[0] = sc->x1;
    oproj.B[1] = oproj.B[2] = nullptr; oproj.bias[1] = oproj.bias[2] = nullptr;
    oproj.C[1] = oproj.C[2] = nullptr;
    gemm_tf32<<<gOne, 256, GEMM_SMEM_BYTES>>>(sc->attn, oproj, x,
                                              S_LEN, N_STATE, N_STATE, 0);

    // LN2
    ln_kernel<<<S_LEN, 256>>>(sc->x1, ln2g, ln2b, sc->h);

    // MLP1 (+exact GELU)
    GemmBatch m1;
    m1.B[0] = W1; m1.bias[0] = b1; m1.C[0] = sc->h2;
    m1.B[1] = m1.B[2] = nullptr; m1.bias[1] = m1.bias[2] = nullptr;
    m1.C[1] = m1.C[2] = nullptr;
    gemm_tf32<<<gMLP1, 256, GEMM_SMEM_BYTES>>>(sc->h, m1, nullptr,
                                               S_LEN, N_MLP, N_STATE, 1);

    // MLP2 (+residual) -> d_out
    GemmBatch m2;
    m2.B[0] = W2; m2.bias[0] = b2; m2.C[0] = out;
    m2.B[1] = m2.B[2] = nullptr; m2.bias[1] = m2.bias[2] = nullptr;
    m2.C[1] = m2.C[2] = nullptr;
    gemm_tf32<<<gOne, 256, GEMM_SMEM_BYTES>>>(sc->h2, m2, sc->x1,
                                              S_LEN, N_STATE, N_MLP, 0);
}

// round 7
// speedup vs baseline: 1.6730x; 1.0041x over previous
#include <cuda_runtime.h>
#include <cuda_bf16.h>
#include <cstdint>
#include <cstddef>

// ---------------------------------------------------------------------------
// Problem constants
// ---------------------------------------------------------------------------
#define S_LEN   1500
#define N_STATE 1280
#define N_HEAD  20
#define D_HEAD  64
#define N_MLP   5120
#define NKT     24          // key tiles of 64

// ---------------------------------------------------------------------------
// Scratch (static device memory; no allocations anywhere)
// ---------------------------------------------------------------------------
struct Scratch {
    float h    [S_LEN * N_STATE];
    float q    [S_LEN * N_STATE];
    float k    [S_LEN * N_STATE];
    float v    [S_LEN * N_STATE];
    float attn [S_LEN * N_STATE];
    float x1   [S_LEN * N_STATE];
    float h2   [S_LEN * N_MLP];
    float part0[S_LEN * N_STATE];
    float part1[S_LEN * N_STATE];
};
__device__ Scratch g_scratch;

// ---------------------------------------------------------------------------
// Helpers
// ---------------------------------------------------------------------------
__device__ __forceinline__ uint32_t f2tf(float x) {
    uint32_t r;
    asm("cvt.rna.tf32.f32 %0, %1;" : "=r"(r) : "f"(x));
    return r;
}
__device__ __forceinline__ float rnd_tf(float x) {
    return __uint_as_float(f2tf(x));
}

// D = A(16x8, tf32, row) * B(8x8, tf32, col) + C, fp32 accum. In-place on acc.
__device__ __forceinline__ void mma_tf32(float acc[4], const uint32_t a[4], const uint32_t b[2]) {
    asm volatile(
        "mma.sync.aligned.m16n8k8.row.col.f32.tf32.tf32.f32 "
        "{%0,%1,%2,%3}, {%4,%5,%6,%7}, {%8,%9}, {%0,%1,%2,%3};\n"
        : "+f"(acc[0]), "+f"(acc[1]), "+f"(acc[2]), "+f"(acc[3])
        : "r"(a[0]), "r"(a[1]), "r"(a[2]), "r"(a[3]),
          "r"(b[0]), "r"(b[1]));
}

__device__ __forceinline__ void cp16(uint32_t dst, const float* src, bool ok) {
    int n = ok ? 16 : 0;   // zfill when out of range
    asm volatile("cp.async.cg.shared.global [%0], [%1], 16, %2;\n"
                 :: "r"(dst), "l"(src), "r"(n));
}
#define CP_COMMIT() asm volatile("cp.async.commit_group;\n")
#define CP_WAIT(N)  asm volatile("cp.async.wait_group %0;\n" :: "n"(N))

__device__ __forceinline__ float gelu_exact(float x) {
    return 0.5f * x * (1.0f + erff(x * 0.7071067811865475f));
}

// ---------------------------------------------------------------------------
// LayerNorm: one block per row, 256 threads, C = 1280 = 5*256.
// Output rounded to tf32 (RNA) — consumed only as GEMM A operand.
// ---------------------------------------------------------------------------
__global__ void ln_kernel(const float* __restrict__ x,
                          const float* __restrict__ gamma,
                          const float* __restrict__ beta,
                          float* __restrict__ out) {
    int row = blockIdx.x;
    int tid = threadIdx.x;
    const float* xr = x + (size_t)row * N_STATE;
    float* orow = out + (size_t)row * N_STATE;

    __shared__ float red[256];
    float local[5];
    float s = 0.f;
#pragma unroll
    for (int i = 0; i < 5; i++) { local[i] = xr[tid + i * 256]; s += local[i]; }
    red[tid] = s; __syncthreads();
#pragma unroll
    for (int o = 128; o > 0; o >>= 1) {
        if (tid < o) red[tid] += red[tid + o];
        __syncthreads();
    }
    float mu = red[0] * (1.0f / N_STATE);
    __syncthreads();

    float vs = 0.f;
#pragma unroll
    for (int i = 0; i < 5; i++) { float d = local[i] - mu; vs += d * d; }
    red[tid] = vs; __syncthreads();
#pragma unroll
    for (int o = 128; o > 0; o >>= 1) {
        if (tid < o) red[tid] += red[tid + o];
        __syncthreads();
    }
    float inv = rsqrtf(red[0] * (1.0f / N_STATE) + 1e-5f);

#pragma unroll
    for (int i = 0; i < 5; i++) {
        int c = tid + i * 256;
        orow[c] = rnd_tf((local[i] - mu) * inv * gamma[c] + beta[c]);
    }
}

// ---------------------------------------------------------------------------
// tf32 MMA GEMM, batched over blockIdx.z:
//   batch mode (aOffK=0): C_z = act(A @ B_z + bias_z), z = different weights
//   split-K mode (aOffK>0): C_z = A[:, z*aOffK:(z+1)*aOffK] @ B_z (partials)
// BM=128, BN=128, BK=32; 256 threads = 8 warps (2m x 4n), warp tile 64x32.
// A fragments: raw bits (producers pre-round to tf32).
// B fragments: RNA-converted in-loop (8 CVT / 16 MMA).
// ---------------------------------------------------------------------------
#define G_BM 128
#define G_BN 128
#define G_BK 32
#define AS_STRIDE 36
#define BS_STRIDE 136
#define AS_BUF (G_BM * AS_STRIDE)                      // 4608 words
#define BS_BUF (G_BK * BS_STRIDE)                      // 4352 words
#define GEMM_SMEM_BYTES ((2 * AS_BUF + 2 * BS_BUF) * 4)   // 71680

struct GemmBatch {
    const float* B[3];
    const float* bias[3];
    float*       C[3];
};

__global__ __launch_bounds__(256, 2)
void gemm_tf32(const float* __restrict__ A, GemmBatch args,
               int M, int N, int K, int lda, int aOffK, int act, int rnd) {
    extern __shared__ uint32_t sm[];

    int z = blockIdx.z;
    const float* __restrict__ Bp   = args.B[z];
    const float* __restrict__ bias = args.bias[z];
    float* __restrict__       C    = args.C[z];

    int tid  = threadIdx.x;
    int warp = tid >> 5, lane = tid & 31;
    int g = lane >> 2, t = lane & 3;
    int wm = warp >> 2;       // 0..1 -> rows wm*64
    int wn = warp & 3;        // 0..3 -> cols wn*32
    int bm0 = blockIdx.y * G_BM;
    int bn0 = blockIdx.x * G_BN;

    uint32_t sbase = (uint32_t)__cvta_generic_to_shared(sm);

    // cp.async mappings
    int arow = tid >> 3;          // 0..31 (+32*i)
    int acol = (tid & 7) * 4;     // k offset
    int brow = tid >> 5;          // 0..7  (+8*i)
    int bcol = (tid & 31) * 4;    // n offset

    const float* aptr = A + (size_t)(bm0 + arow) * lda + (size_t)z * aOffK + acol;
    const float* bptr = Bp + (size_t)brow * N + bn0 + bcol;

    auto loadg = [&](int k0, int buf) {
        uint32_t ad = sbase + (buf * AS_BUF) * 4;
#pragma unroll
        for (int i = 0; i < 4; i++) {
            int r = bm0 + arow + 32 * i;
            cp16(ad + ((arow + 32 * i) * AS_STRIDE + acol) * 4,
                 aptr + (size_t)(32 * i) * lda + k0, r < M);
        }
        uint32_t bd = sbase + (2 * AS_BUF + buf * BS_BUF) * 4;
#pragma unroll
        for (int i = 0; i < 4; i++) {
            cp16(bd + ((brow + 8 * i) * BS_STRIDE + bcol) * 4,
                 bptr + (size_t)(k0 + 8 * i) * N, true);
        }
        CP_COMMIT();
    };

    float acc[4][4][4];
#pragma unroll
    for (int i = 0; i < 4; i++)
#pragma unroll
        for (int j = 0; j < 4; j++)
#pragma unroll
            for (int r = 0; r < 4; r++) acc[i][j][r] = 0.f;

    int nk = K / G_BK;
    loadg(0, 0);

    for (int kt = 0; kt < nk; kt++) {
        int buf = kt & 1;
        if (kt + 1 < nk) { loadg((kt + 1) * G_BK, buf ^ 1); CP_WAIT(1); }
        else             { CP_WAIT(0); }
        __syncthreads();

        const uint32_t* ab = sm + buf * AS_BUF;
        const uint32_t* bb = sm + 2 * AS_BUF + buf * BS_BUF;
#pragma unroll
        for (int ks = 0; ks < 4; ks++) {
            uint32_t af[4][4], bf[4][2];
#pragma unroll
            for (int i = 0; i < 4; i++) {
                const uint32_t* base = ab + (wm * 64 + i * 16 + g) * AS_STRIDE + ks * 8 + t;
                af[i][0] = base[0];
                af[i][1] = base[8 * AS_STRIDE];
                af[i][2] = base[4];
                af[i][3] = base[8 * AS_STRIDE + 4];
            }
#pragma unroll
            for (int j = 0; j < 4; j++) {
                const uint32_t* base = bb + (ks * 8 + t) * BS_STRIDE + wn * 32 + j * 8 + g;
                bf[j][0] = f2tf(__uint_as_float(base[0]));
                bf[j][1] = f2tf(__uint_as_float(base[4 * BS_STRIDE]));
            }
#pragma unroll
            for (int i = 0; i < 4; i++)
#pragma unroll
                for (int j = 0; j < 4; j++)
                    mma_tf32(acc[i][j], af[i], bf[j]);
        }
        __syncthreads();   // before next slab's cp.async overwrites this buffer
    }

    // epilogue
#pragma unroll
    for (int i = 0; i < 4; i++) {
        int r0 = bm0 + wm * 64 + i * 16 + g;
        int r1 = r0 + 8;
#pragma unroll
        for (int j = 0; j < 4; j++) {
            int c = bn0 + wn * 32 + j * 8 + 2 * t;
            float bb0 = bias ? bias[c]     : 0.f;
            float bb1 = bias ? bias[c + 1] : 0.f;
            if (r0 < M) {
                float v0 = acc[i][j][0] + bb0, v1 = acc[i][j][1] + bb1;
                if (act) { v0 = gelu_exact(v0); v1 = gelu_exact(v1); }
                if (rnd) { v0 = rnd_tf(v0); v1 = rnd_tf(v1); }
                *(float2*)&C[(size_t)r0 * N + c] = make_float2(v0, v1);
            }
            if (r1 < M) {
                float v2 = acc[i][j][2] + bb0, v3 = acc[i][j][3] + bb1;
                if (act) { v2 = gelu_exact(v2); v3 = gelu_exact(v3); }
                if (rnd) { v2 = rnd_tf(v2); v3 = rnd_tf(v3); }
                *(float2*)&C[(size_t)r1 * N + c] = make_float2(v2, v3);
            }
        }
    }
}

// ---------------------------------------------------------------------------
// Split-K reduce: out = p0 + p1 + bias + res   (N = N_STATE columns)
// ---------------------------------------------------------------------------
__global__ void splitk_reduce(const float* __restrict__ p0,
                              const float* __restrict__ p1,
                              const float* __restrict__ bias,
                              const float* __restrict__ res,
                              float* __restrict__ out) {
    int i = blockIdx.x * blockDim.x + threadIdx.x;           // float4 index
    const int total4 = S_LEN * N_STATE / 4;
    if (i >= total4) return;
    float4 a = ((const float4*)p0)[i];
    float4 b = ((const float4*)p1)[i];
    float4 r = ((const float4*)res)[i];
    int c = (i * 4) % N_STATE;
    float4 bb = *(const float4*)&bias[c];
    float4 o;
    o.x = a.x + b.x + bb.x + r.x;
    o.y = a.y + b.y + bb.y + r.y;
    o.z = a.z + b.z + bb.z + r.z;
    o.w = a.w + b.w + bb.w + r.w;
    ((float4*)out)[i] = o;
}

// ---------------------------------------------------------------------------
// Fused flash attention (non-causal).
// Block = (q-tile of 128, head), 256 threads = 8 warps, warp owns 16 q rows.
// Double-buffered K/V tiles via cp.async (prefetch issued after the one
// barrier per tile, so load latency hides behind QK+softmax+PV).
// P lives in a dedicated warp-private smem region -> no extra barrier.
// Q/K/V are tf32-exact in gmem (producers round); only P needs f2tf.
//   K/P stride 68: frag banks (4g+t) conflict-free
//   V   stride 72: frag banks (8t+g) conflict-free
// smem = 2*64*68 + 2*64*72 + 128*68 words = 106496 B -> 2 CTAs/SM.
// ---------------------------------------------------------------------------
#define KB_STRIDE 68
#define VB_STRIDE 72
#define KBUF_W (64 * KB_STRIDE)               // 4352
#define VBUF_W (64 * VB_STRIDE)               // 4608
#define PREG_OFF (2 * KBUF_W + 2 * VBUF_W)    // 17920
#define ATTN_SMEM_BYTES ((PREG_OFF + 128 * KB_STRIDE) * 4)   // 106496

__global__ __launch_bounds__(256, 2)
void attn_kernel(const float* __restrict__ qp, const float* __restrict__ kp,
                 const float* __restrict__ vp, float* __restrict__ out) {
    extern __shared__ uint32_t smn[];

    int qt = blockIdx.x;
    int h  = blockIdx.y;
    int tid = threadIdx.x, warp = tid >> 5, lane = tid & 31;
    int g = lane >> 2, t = lane & 3;
    int qrow0 = qt * 128 + warp * 16;
    uint32_t sbase = (uint32_t)__cvta_generic_to_shared(smn);

    // ---- preload Q fragments (raw bits; q is tf32-exact, *0.125 is exact) ----
    uint32_t qf[8][4];
    {
        int rA = qrow0 + g, rB = qrow0 + g + 8;
        bool okA = rA < S_LEN, okB = rB < S_LEN;
        const float* qA = qp + (size_t)rA * N_STATE + h * D_HEAD;
        const float* qB = qp + (size_t)rB * N_STATE + h * D_HEAD;
#pragma unroll
        for (int ks = 0; ks < 8; ks++) {
            float a0 = okA ? qA[ks * 8 + t]     : 0.f;
            float a1 = okB ? qB[ks * 8 + t]     : 0.f;
            float a2 = okA ? qA[ks * 8 + t + 4] : 0.f;
            float a3 = okB ? qB[ks * 8 + t + 4] : 0.f;
            qf[ks][0] = __float_as_uint(a0 * 0.125f);
            qf[ks][1] = __float_as_uint(a1 * 0.125f);
            qf[ks][2] = __float_as_uint(a2 * 0.125f);
            qf[ks][3] = __float_as_uint(a3 * 0.125f);
        }
    }

    float of[8][4];
#pragma unroll
    for (int j = 0; j < 8; j++)
#pragma unroll
        for (int r = 0; r < 4; r++) of[j][r] = 0.f;
    float m0 = -1e30f, m1 = -1e30f, l0 = 0.f, l1 = 0.f;

    int lrow = tid >> 4;            // 0..15
    int lc4  = (tid & 15) * 4;      // 0..60
    const float* kpb = kp + h * D_HEAD + lc4;
    const float* vpb = vp + h * D_HEAD + lc4;

    auto issue = [&](int kt, int buf) {
#pragma unroll
        for (int p = 0; p < 4; p++) {
            int row = lrow + p * 16;
            int gk = kt * 64 + row;
            cp16(sbase + (buf * KBUF_W + row * KB_STRIDE + lc4) * 4,
                 kpb + (size_t)gk * N_STATE, gk < S_LEN);
        }
#pragma unroll
        for (int p = 0; p < 4; p++) {
            int row = lrow + p * 16;
            int gk = kt * 64 + row;
            cp16(sbase + (2 * KBUF_W + buf * VBUF_W + row * VB_STRIDE + lc4) * 4,
                 vpb + (size_t)gk * N_STATE, gk < S_LEN);
        }
        CP_COMMIT();
    };

    issue(0, 0);

    for (int kt = 0; kt < NKT; kt++) {
        int buf = kt & 1;
        CP_WAIT(0);          // current tile resident
        __syncthreads();     // all warps done with previous tile's buffers
        if (kt + 1 < NKT) issue(kt + 1, buf ^ 1);   // prefetch overlaps compute

        const uint32_t* Kb = smn + buf * KBUF_W;
        const uint32_t* Vb = smn + 2 * KBUF_W + buf * VBUF_W;

        // ---- S = Q * K^T  (16 x 64 per warp) ----
        float sacc[8][4];
#pragma unroll
        for (int j = 0; j < 8; j++)
#pragma unroll
            for (int r = 0; r < 4; r++) sacc[j][r] = 0.f;

#pragma unroll
        for (int ks = 0; ks < 8; ks++) {
#pragma unroll
            for (int j = 0; j < 8; j++) {
                uint32_t bf[2];
                const uint32_t* base = Kb + (j * 8 + g) * KB_STRIDE + ks * 8 + t;
                bf[0] = base[0];
                bf[1] = base[4];
                mma_tf32(sacc[j], qf[ks], bf);
            }
        }

        // ---- mask padded keys (only last tile) ----
        if (kt == NKT - 1) {
#pragma unroll
            for (int j = 0; j < 8; j++) {
                int c = j * 8 + 2 * t;
                if (1472 + c     >= S_LEN) { sacc[j][0] = -1e30f; sacc[j][2] = -1e30f; }
                if (1472 + c + 1 >= S_LEN) { sacc[j][1] = -1e30f; sacc[j][3] = -1e30f; }
            }
        }

        // ---- online softmax ----
        float tm0 = -1e30f, tm1 = -1e30f;
#pragma unroll
        for (int j = 0; j < 8; j++) {
            tm0 = fmaxf(tm0, fmaxf(sacc[j][0], sacc[j][1]));
            tm1 = fmaxf(tm1, fmaxf(sacc[j][2], sacc[j][3]));
        }
        tm0 = fmaxf(tm0, __shfl_xor_sync(0xffffffffu, tm0, 1));
        tm0 = fmaxf(tm0, __shfl_xor_sync(0xffffffffu, tm0, 2));
        tm1 = fmaxf(tm1, __shfl_xor_sync(0xffffffffu, tm1, 1));
        tm1 = fmaxf(tm1, __shfl_xor_sync(0xffffffffu, tm1, 2));

        float nm0 = fmaxf(m0, tm0), nm1 = fmaxf(m1, tm1);
        float c0 = __expf(m0 - nm0), c1 = __expf(m1 - nm1);
        l0 *= c0; l1 *= c1;
#pragma unroll
        for (int j = 0; j < 8; j++) {
            of[j][0] *= c0; of[j][1] *= c0;
            of[j][2] *= c1; of[j][3] *= c1;
        }
        m0 = nm0; m1 = nm1;

        // ---- P = exp(S - m), rounded to tf32, into warp-private smem ----
        uint32_t* Pw = smn + PREG_OFF + (warp * 16) * KB_STRIDE;
        float ps0 = 0.f, ps1 = 0.f;
#pragma unroll
        for (int j = 0; j < 8; j++) {
            uint32_t b0 = f2tf(__expf(sacc[j][0] - nm0));
            uint32_t b1 = f2tf(__expf(sacc[j][1] - nm0));
            uint32_t b2 = f2tf(__expf(sacc[j][2] - nm1));
            uint32_t b3 = f2tf(__expf(sacc[j][3] - nm1));
            ps0 += __uint_as_float(b0) + __uint_as_float(b1);
            ps1 += __uint_as_float(b2) + __uint_as_float(b3);
            int c = j * 8 + 2 * t;
            uint2 pa = {b0, b1};
            uint2 pc = {b2, b3};
            *(uint2*)&Pw[g       * KB_STRIDE + c] = pa;
            *(uint2*)&Pw[(g + 8) * KB_STRIDE + c] = pc;
        }
        ps0 += __shfl_xor_sync(0xffffffffu, ps0, 1);
        ps0 += __shfl_xor_sync(0xffffffffu, ps0, 2);
        ps1 += __shfl_xor_sync(0xffffffffu, ps1, 1);
        ps1 += __shfl_xor_sync(0xffffffffu, ps1, 2);
        l0 += ps0; l1 += ps1;
        __syncwarp();

        // ---- O += P * V (warp-private P) ----
#pragma unroll
        for (int ks = 0; ks < 8; ks++) {
            uint32_t af[4];
            const uint32_t* pb = Pw + g * KB_STRIDE + ks * 8 + t;
            af[0] = pb[0];
            af[1] = pb[8 * KB_STRIDE];
            af[2] = pb[4];
            af[3] = pb[8 * KB_STRIDE + 4];
#pragma unroll
            for (int j = 0; j < 8; j++) {
                uint32_t bf[2];
                const uint32_t* vb = Vb + (ks * 8 + t) * VB_STRIDE + j * 8 + g;
                bf[0] = vb[0];
                bf[1] = vb[4 * VB_STRIDE];
                mma_tf32(of[j], af, bf);
            }
        }
    }

    // ---- finalize + store (rounded: feeds O-proj as A operand) ----
    float inv0 = 1.0f / l0, inv1 = 1.0f / l1;
    int r0 = qrow0 + g, r1 = qrow0 + g + 8;
#pragma unroll
    for (int j = 0; j < 8; j++) {
        int c = h * D_HEAD + j * 8 + 2 * t;
        if (r0 < S_LEN)
            *(float2*)&out[(size_t)r0 * N_STATE + c] =
                make_float2(rnd_tf(of[j][0] * inv0), rnd_tf(of[j][1] * inv0));
        if (r1 < S_LEN)
            *(float2*)&out[(size_t)r1 * N_STATE + c] =
                make_float2(rnd_tf(of[j][2] * inv1), rnd_tf(of[j][3] * inv1));
    }
}

// ---------------------------------------------------------------------------
// Launch: 9 kernels on the default stream (graph-capturable, alloc-free)
// ---------------------------------------------------------------------------
extern "C" void kernel_launch(void* const* d_in, const int* in_sizes, int n_in,
                              void* d_out, int out_size) {
    (void)in_sizes; (void)n_in; (void)out_size;

    const float* x    = (const float*)d_in[0];
    const float* Wq   = (const float*)d_in[1];
    const float* bq   = (const float*)d_in[2];
    const float* Wk   = (const float*)d_in[3];
    const float* Wv   = (const float*)d_in[4];
    const float* bv   = (const float*)d_in[5];
    const float* Wo   = (const float*)d_in[6];
    const float* bo   = (const float*)d_in[7];
    const float* ln1g = (const float*)d_in[8];
    const float* ln1b = (const float*)d_in[9];
    const float* ln2g = (const float*)d_in[10];
    const float* ln2b = (const float*)d_in[11];
    const float* W1   = (const float*)d_in[12];
    const float* b1   = (const float*)d_in[13];
    const float* W2   = (const float*)d_in[14];
    const float* b2   = (const float*)d_in[15];
    float* out = (float*)d_out;

    Scratch* sc = nullptr;
    cudaGetSymbolAddress((void**)&sc, g_scratch);

    cudaFuncSetAttribute(gemm_tf32,
                         cudaFuncAttributeMaxDynamicSharedMemorySize,
                         GEMM_SMEM_BYTES);
    cudaFuncSetAttribute(attn_kernel,
                         cudaFuncAttributeMaxDynamicSharedMemorySize,
                         ATTN_SMEM_BYTES);

    dim3 gQKV (N_STATE / G_BN, (S_LEN + G_BM - 1) / G_BM, 3);  // (10,12,3)
    dim3 gSpl (N_STATE / G_BN, (S_LEN + G_BM - 1) / G_BM, 2);  // (10,12,2)
    dim3 gMLP1(N_MLP  / G_BN, (S_LEN + G_BM - 1) / G_BM, 1);   // (40,12,1)
    const int red_grid = (S_LEN * N_STATE / 4 + 255) / 256;

    // LN1 (output tf32-rounded)
    ln_kernel<<<S_LEN, 256>>>(x, ln1g, ln1b, sc->h);

    // QKV projections (one fused launch, shared A; outputs tf32-rounded)
    GemmBatch qkv;
    qkv.B[0] = Wq; qkv.bias[0] = bq;      qkv.C[0] = sc->q;
    qkv.B[1] = Wk; qkv.bias[1] = nullptr; qkv.C[1] = sc->k;
    qkv.B[2] = Wv; qkv.bias[2] = bv;      qkv.C[2] = sc->v;
    gemm_tf32<<<gQKV, 256, GEMM_SMEM_BYTES>>>(sc->h, qkv,
        S_LEN, N_STATE, N_STATE, /*lda=*/N_STATE, /*aOffK=*/0, 0, /*rnd=*/1);

    // attention (output tf32-rounded)
    attn_kernel<<<dim3(12, N_HEAD), 256, ATTN_SMEM_BYTES>>>(sc->q, sc->k, sc->v, sc->attn);

    // O-proj split-K x2 -> partials, then reduce (+bias +residual x) -> x1
    GemmBatch opr;
    opr.B[0] = Wo;                       opr.bias[0] = nullptr; opr.C[0] = sc->part0;
    opr.B[1] = Wo + (size_t)640 * N_STATE; opr.bias[1] = nullptr; opr.C[1] = sc->part1;
    opr.B[2] = nullptr; opr.bias[2] = nullptr; opr.C[2] = nullptr;
    gemm_tf32<<<gSpl, 256, GEMM_SMEM_BYTES>>>(sc->attn, opr,
        S_LEN, N_STATE, /*K=*/640, /*lda=*/N_STATE, /*aOffK=*/640, 0, 0);
    splitk_reduce<<<red_grid, 256>>>(sc->part0, sc->part1, bo, x, sc->x1);

    // LN2 (output tf32-rounded)
    ln_kernel<<<S_LEN, 256>>>(sc->x1, ln2g, ln2b, sc->h);

    // MLP1 (+exact GELU; output tf32-rounded)
    GemmBatch m1;
    m1.B[0] = W1; m1.bias[0] = b1; m1.C[0] = sc->h2;
    m1.B[1] = m1.B[2] = nullptr; m1.bias[1] = m1.bias[2] = nullptr;
    m1.C[1] = m1.C[2] = nullptr;
    gemm_tf32<<<gMLP1, 256, GEMM_SMEM_BYTES>>>(sc->h, m1,
        S_LEN, N_MLP, N_STATE, /*lda=*/N_STATE, /*aOffK=*/0, /*act=*/1, /*rnd=*/1);

    // MLP2 split-K x2 -> partials, then reduce (+bias +residual x1) -> out
    GemmBatch m2;
    m2.B[0] = W2;                          m2.bias[0] = nullptr; m2.C[0] = sc->part0;
    m2.B[1] = W2 + (size_t)2560 * N_STATE; m2.bias[1] = nullptr; m2.C[1] = sc->part1;
    m2.B[2] = nullptr; m2.bias[2] = nullptr; m2.C[2] = nullptr;
    gemm_tf32<<<gSpl, 256, GEMM_SMEM_BYTES>>>(sc->h2, m2,
        S_LEN, N_STATE, /*K=*/2560, /*lda=*/N_MLP, /*aOffK=*/2560, 0, 0);
    splitk_reduce<<<red_grid, 256>>>(sc->part0, sc->part1, b2, sc->x1, out);
}

// round 8
// speedup vs baseline: 1.7005x; 1.0165x over previous
#include <cuda_runtime.h>
#include <cuda_bf16.h>
#include <cstdint>
#include <cstddef>

// ---------------------------------------------------------------------------
// Problem constants
// ---------------------------------------------------------------------------
#define S_LEN   1500
#define N_STATE 1280
#define N_HEAD  20
#define D_HEAD  64
#define N_MLP   5120
#define NKT     24          // key tiles of 64

// ---------------------------------------------------------------------------
// Scratch (static device memory; no allocations anywhere)
// ---------------------------------------------------------------------------
struct Scratch {
    float h    [S_LEN * N_STATE];
    float q    [S_LEN * N_STATE];
    float k    [S_LEN * N_STATE];
    float v    [S_LEN * N_STATE];
    float attn [S_LEN * N_STATE];
    float x1   [S_LEN * N_STATE];
    float h2   [S_LEN * N_MLP];
    float part0[S_LEN * N_STATE];
    float part1[S_LEN * N_STATE];
};
__device__ Scratch g_scratch;

// ---------------------------------------------------------------------------
// Helpers
// ---------------------------------------------------------------------------
__device__ __forceinline__ uint32_t f2tf(float x) {
    uint32_t r;
    asm("cvt.rna.tf32.f32 %0, %1;" : "=r"(r) : "f"(x));
    return r;
}
__device__ __forceinline__ float rnd_tf(float x) {
    return __uint_as_float(f2tf(x));
}

// D = A(16x8, tf32, row) * B(8x8, tf32, col) + C, fp32 accum. In-place on acc.
__device__ __forceinline__ void mma_tf32(float acc[4], const uint32_t a[4], const uint32_t b[2]) {
    asm volatile(
        "mma.sync.aligned.m16n8k8.row.col.f32.tf32.tf32.f32 "
        "{%0,%1,%2,%3}, {%4,%5,%6,%7}, {%8,%9}, {%0,%1,%2,%3};\n"
        : "+f"(acc[0]), "+f"(acc[1]), "+f"(acc[2]), "+f"(acc[3])
        : "r"(a[0]), "r"(a[1]), "r"(a[2]), "r"(a[3]),
          "r"(b[0]), "r"(b[1]));
}

__device__ __forceinline__ void cp16(uint32_t dst, const float* src, bool ok) {
    int n = ok ? 16 : 0;   // zfill when out of range
    asm volatile("cp.async.cg.shared.global [%0], [%1], 16, %2;\n"
                 :: "r"(dst), "l"(src), "r"(n));
}
#define CP_COMMIT() asm volatile("cp.async.commit_group;\n")
#define CP_WAIT(N)  asm volatile("cp.async.wait_group %0;\n" :: "n"(N))

__device__ __forceinline__ float gelu_exact(float x) {
    return 0.5f * x * (1.0f + erff(x * 0.7071067811865475f));
}

// ---------------------------------------------------------------------------
// LayerNorm: one block per row, 256 threads, C = 1280 = 5*256.
// Output rounded to tf32 (RNA) — consumed only as GEMM A operand.
// ---------------------------------------------------------------------------
__global__ void ln_kernel(const float* __restrict__ x,
                          const float* __restrict__ gamma,
                          const float* __restrict__ beta,
                          float* __restrict__ out) {
    int row = blockIdx.x;
    int tid = threadIdx.x;
    const float* xr = x + (size_t)row * N_STATE;
    float* orow = out + (size_t)row * N_STATE;

    __shared__ float red[256];
    float local[5];
    float s = 0.f;
#pragma unroll
    for (int i = 0; i < 5; i++) { local[i] = xr[tid + i * 256]; s += local[i]; }
    red[tid] = s; __syncthreads();
#pragma unroll
    for (int o = 128; o > 0; o >>= 1) {
        if (tid < o) red[tid] += red[tid + o];
        __syncthreads();
    }
    float mu = red[0] * (1.0f / N_STATE);
    __syncthreads();

    float vs = 0.f;
#pragma unroll
    for (int i = 0; i < 5; i++) { float d = local[i] - mu; vs += d * d; }
    red[tid] = vs; __syncthreads();
#pragma unroll
    for (int o = 128; o > 0; o >>= 1) {
        if (tid < o) red[tid] += red[tid + o];
        __syncthreads();
    }
    float inv = rsqrtf(red[0] * (1.0f / N_STATE) + 1e-5f);

#pragma unroll
    for (int i = 0; i < 5; i++) {
        int c = tid + i * 256;
        orow[c] = rnd_tf((local[i] - mu) * inv * gamma[c] + beta[c]);
    }
}

// ---------------------------------------------------------------------------
// tf32 MMA GEMM, batched over blockIdx.z:
//   batch mode (aOffK=0): C_z = act(A @ B_z + bias_z), z = different weights
//   split-K mode (aOffK>0): C_z = A[:, z*aOffK:(z+1)*aOffK] @ B_z (partials)
// BM=128, BN=128, BK=32; 256 threads = 8 warps (2m x 4n), warp tile 64x32.
// 3-stage cp.async pipeline, ONE __syncthreads per 32-deep k-slab:
//   stage (kt+2)%3 == (kt-1)%3 is reusable once the barrier at iter kt passes.
// A fragments: raw bits (producers pre-round to tf32).
// B fragments: RNA-converted in-loop (8 CVT / 16 MMA).
// ---------------------------------------------------------------------------
#define G_BM 128
#define G_BN 128
#define G_BK 32
#define AS_STRIDE 36
#define BS_STRIDE 136
#define AS_BUF (G_BM * AS_STRIDE)                      // 4608 words
#define BS_BUF (G_BK * BS_STRIDE)                      // 4352 words
#define STAGE_W (AS_BUF + BS_BUF)                      // 8960 words
#define GEMM_SMEM_BYTES (3 * STAGE_W * 4)              // 107520

struct GemmBatch {
    const float* B[3];
    const float* bias[3];
    float*       C[3];
};

__global__ __launch_bounds__(256, 2)
void gemm_tf32(const float* __restrict__ A, GemmBatch args,
               int M, int N, int K, int lda, int aOffK, int act, int rnd) {
    extern __shared__ uint32_t sm[];

    int z = blockIdx.z;
    const float* __restrict__ Bp   = args.B[z];
    const float* __restrict__ bias = args.bias[z];
    float* __restrict__       C    = args.C[z];

    int tid  = threadIdx.x;
    int warp = tid >> 5, lane = tid & 31;
    int g = lane >> 2, t = lane & 3;
    int wm = warp >> 2;       // 0..1 -> rows wm*64
    int wn = warp & 3;        // 0..3 -> cols wn*32
    int bm0 = blockIdx.y * G_BM;
    int bn0 = blockIdx.x * G_BN;

    uint32_t sbase = (uint32_t)__cvta_generic_to_shared(sm);

    // cp.async mappings
    int arow = tid >> 3;          // 0..31 (+32*i)
    int acol = (tid & 7) * 4;     // k offset
    int brow = tid >> 5;          // 0..7  (+8*i)
    int bcol = (tid & 31) * 4;    // n offset

    const float* aptr = A + (size_t)(bm0 + arow) * lda + (size_t)z * aOffK + acol;
    const float* bptr = Bp + (size_t)brow * N + bn0 + bcol;

    auto loadg = [&](int k0, int stg) {
        uint32_t ad = sbase + (stg * STAGE_W) * 4;
#pragma unroll
        for (int i = 0; i < 4; i++) {
            int r = bm0 + arow + 32 * i;
            cp16(ad + ((arow + 32 * i) * AS_STRIDE + acol) * 4,
                 aptr + (size_t)(32 * i) * lda + k0, r < M);
        }
        uint32_t bd = ad + AS_BUF * 4;
#pragma unroll
        for (int i = 0; i < 4; i++) {
            cp16(bd + ((brow + 8 * i) * BS_STRIDE + bcol) * 4,
                 bptr + (size_t)(k0 + 8 * i) * N, true);
        }
        CP_COMMIT();
    };

    float acc[4][4][4];
#pragma unroll
    for (int i = 0; i < 4; i++)
#pragma unroll
        for (int j = 0; j < 4; j++)
#pragma unroll
            for (int r = 0; r < 4; r++) acc[i][j][r] = 0.f;

    int nk = K / G_BK;
    loadg(0, 0);
    if (nk > 1) loadg(G_BK, 1);

    int stg = 0;
    for (int kt = 0; kt < nk; kt++) {
        if (kt + 1 < nk) { CP_WAIT(1); }
        else             { CP_WAIT(0); }
        __syncthreads();   // stage kt ready; all warps done with stage kt-1
        if (kt + 2 < nk) {
            int ns = stg + 2; if (ns >= 3) ns -= 3;
            loadg((kt + 2) * G_BK, ns);
        }

        const uint32_t* ab = sm + stg * STAGE_W;
        const uint32_t* bb = ab + AS_BUF;
#pragma unroll
        for (int ks = 0; ks < 4; ks++) {
            uint32_t af[4][4], bf[4][2];
#pragma unroll
            for (int i = 0; i < 4; i++) {
                const uint32_t* base = ab + (wm * 64 + i * 16 + g) * AS_STRIDE + ks * 8 + t;
                af[i][0] = base[0];
                af[i][1] = base[8 * AS_STRIDE];
                af[i][2] = base[4];
                af[i][3] = base[8 * AS_STRIDE + 4];
            }
#pragma unroll
            for (int j = 0; j < 4; j++) {
                const uint32_t* base = bb + (ks * 8 + t) * BS_STRIDE + wn * 32 + j * 8 + g;
                bf[j][0] = f2tf(__uint_as_float(base[0]));
                bf[j][1] = f2tf(__uint_as_float(base[4 * BS_STRIDE]));
            }
#pragma unroll
            for (int i = 0; i < 4; i++)
#pragma unroll
                for (int j = 0; j < 4; j++)
                    mma_tf32(acc[i][j], af[i], bf[j]);
        }
        if (++stg == 3) stg = 0;
    }

    // epilogue
#pragma unroll
    for (int i = 0; i < 4; i++) {
        int r0 = bm0 + wm * 64 + i * 16 + g;
        int r1 = r0 + 8;
#pragma unroll
        for (int j = 0; j < 4; j++) {
            int c = bn0 + wn * 32 + j * 8 + 2 * t;
            float bb0 = bias ? bias[c]     : 0.f;
            float bb1 = bias ? bias[c + 1] : 0.f;
            if (r0 < M) {
                float v0 = acc[i][j][0] + bb0, v1 = acc[i][j][1] + bb1;
                if (act) { v0 = gelu_exact(v0); v1 = gelu_exact(v1); }
                if (rnd) { v0 = rnd_tf(v0); v1 = rnd_tf(v1); }
                *(float2*)&C[(size_t)r0 * N + c] = make_float2(v0, v1);
            }
            if (r1 < M) {
                float v2 = acc[i][j][2] + bb0, v3 = acc[i][j][3] + bb1;
                if (act) { v2 = gelu_exact(v2); v3 = gelu_exact(v3); }
                if (rnd) { v2 = rnd_tf(v2); v3 = rnd_tf(v3); }
                *(float2*)&C[(size_t)r1 * N + c] = make_float2(v2, v3);
            }
        }
    }
}

// ---------------------------------------------------------------------------
// Split-K reduce: out = p0 + p1 + bias + res   (N = N_STATE columns)
// ---------------------------------------------------------------------------
__global__ void splitk_reduce(const float* __restrict__ p0,
                              const float* __restrict__ p1,
                              const float* __restrict__ bias,
                              const float* __restrict__ res,
                              float* __restrict__ out) {
    int i = blockIdx.x * blockDim.x + threadIdx.x;           // float4 index
    const int total4 = S_LEN * N_STATE / 4;
    if (i >= total4) return;
    float4 a = ((const float4*)p0)[i];
    float4 b = ((const float4*)p1)[i];
    float4 r = ((const float4*)res)[i];
    int c = (i * 4) % N_STATE;
    float4 bb = *(const float4*)&bias[c];
    float4 o;
    o.x = a.x + b.x + bb.x + r.x;
    o.y = a.y + b.y + bb.y + r.y;
    o.z = a.z + b.z + bb.z + r.z;
    o.w = a.w + b.w + bb.w + r.w;
    ((float4*)out)[i] = o;
}

// ---------------------------------------------------------------------------
// Fused flash attention (non-causal), k-dim permutation trick.
// Block = (q-tile of 128, head), 256 threads = 8 warps, warp owns 16 q rows.
//
// The contraction dim of each MMA is permuted so that MMA-k index t maps to
// element 2t and t+4 to 2t+1 (applied consistently to BOTH operands, so the
// dot product is unchanged):
//  * QK^T: Q frags load dims (2t, 2t+1); K B-frags become two ADJACENT smem
//    words -> one LDS.64 per MMA (stride 72: banks 8g+2t pairwise free).
//  * P.V : with keys permuted the same way, the S/P C-fragment layout
//    (S[g][2t], S[g][2t+1], S[g+8][2t], S[g+8][2t+1]) IS the PV A-fragment
//    -> P never touches smem (no stores, no loads, no extra barrier).
//    V B-frag rows 2t/2t+1, stride 68 -> banks 8t+g (+4) conflict-free.
// Double-buffered K/V via cp.async; one __syncthreads per tile.
// smem = 2*64*72 + 2*64*68 words = 71680 B -> 2 CTAs/SM.
// ---------------------------------------------------------------------------
#define KB_STRIDE 72
#define VB_STRIDE 68
#define KBUF_W (64 * KB_STRIDE)               // 4608
#define VBUF_W (64 * VB_STRIDE)               // 4352
#define ATTN_SMEM_BYTES ((2 * KBUF_W + 2 * VBUF_W) * 4)   // 71680

__global__ __launch_bounds__(256, 2)
void attn_kernel(const float* __restrict__ qp, const float* __restrict__ kp,
                 const float* __restrict__ vp, float* __restrict__ out) {
    extern __shared__ uint32_t smn[];

    int qt = blockIdx.x;
    int h  = blockIdx.y;
    int tid = threadIdx.x, warp = tid >> 5, lane = tid & 31;
    int g = lane >> 2, t = lane & 3;
    int qrow0 = qt * 128 + warp * 16;
    uint32_t sbase = (uint32_t)__cvta_generic_to_shared(smn);

    // ---- preload Q fragments with permuted k: word0<->dim 2t, word2<->2t+1 ----
    uint32_t qf[8][4];
    {
        int rA = qrow0 + g, rB = qrow0 + g + 8;
        bool okA = rA < S_LEN, okB = rB < S_LEN;
        const float* qA = qp + (size_t)rA * N_STATE + h * D_HEAD;
        const float* qB = qp + (size_t)rB * N_STATE + h * D_HEAD;
#pragma unroll
        for (int ks = 0; ks < 8; ks++) {
            int d0 = ks * 8 + 2 * t;
            float a0 = okA ? qA[d0]     : 0.f;
            float a1 = okB ? qB[d0]     : 0.f;
            float a2 = okA ? qA[d0 + 1] : 0.f;
            float a3 = okB ? qB[d0 + 1] : 0.f;
            qf[ks][0] = __float_as_uint(a0 * 0.125f);
            qf[ks][1] = __float_as_uint(a1 * 0.125f);
            qf[ks][2] = __float_as_uint(a2 * 0.125f);
            qf[ks][3] = __float_as_uint(a3 * 0.125f);
        }
    }

    float of[8][4];
#pragma unroll
    for (int j = 0; j < 8; j++)
#pragma unroll
        for (int r = 0; r < 4; r++) of[j][r] = 0.f;
    float m0 = -1e30f, m1 = -1e30f, l0 = 0.f, l1 = 0.f;

    int lrow = tid >> 4;            // 0..15
    int lc4  = (tid & 15) * 4;      // 0..60
    const float* kpb = kp + h * D_HEAD + lc4;
    const float* vpb = vp + h * D_HEAD + lc4;

    auto issue = [&](int kt, int buf) {
#pragma unroll
        for (int p = 0; p < 4; p++) {
            int row = lrow + p * 16;
            int gk = kt * 64 + row;
            cp16(sbase + (buf * KBUF_W + row * KB_STRIDE + lc4) * 4,
                 kpb + (size_t)gk * N_STATE, gk < S_LEN);
        }
#pragma unroll
        for (int p = 0; p < 4; p++) {
            int row = lrow + p * 16;
            int gk = kt * 64 + row;
            cp16(sbase + (2 * KBUF_W + buf * VBUF_W + row * VB_STRIDE + lc4) * 4,
                 vpb + (size_t)gk * N_STATE, gk < S_LEN);
        }
        CP_COMMIT();
    };

    issue(0, 0);

    for (int kt = 0; kt < NKT; kt++) {
        int buf = kt & 1;
        CP_WAIT(0);          // current tile resident
        __syncthreads();     // all warps done with previous tile's buffers
        if (kt + 1 < NKT) issue(kt + 1, buf ^ 1);   // prefetch overlaps compute

        const uint32_t* Kb = smn + buf * KBUF_W;
        const uint32_t* Vb = smn + 2 * KBUF_W + buf * VBUF_W;

        // ---- S = Q * K^T  (16 x 64 per warp); B-frag = one LDS.64 ----
        float sacc[8][4];
#pragma unroll
        for (int j = 0; j < 8; j++)
#pragma unroll
            for (int r = 0; r < 4; r++) sacc[j][r] = 0.f;

#pragma unroll
        for (int ks = 0; ks < 8; ks++) {
#pragma unroll
            for (int j = 0; j < 8; j++) {
                uint2 kb = *(const uint2*)&Kb[(j * 8 + g) * KB_STRIDE + ks * 8 + 2 * t];
                uint32_t bf[2] = {kb.x, kb.y};
                mma_tf32(sacc[j], qf[ks], bf);
            }
        }

        // ---- mask padded keys (only last tile) ----
        if (kt == NKT - 1) {
#pragma unroll
            for (int j = 0; j < 8; j++) {
                int c = j * 8 + 2 * t;
                if (1472 + c     >= S_LEN) { sacc[j][0] = -1e30f; sacc[j][2] = -1e30f; }
                if (1472 + c + 1 >= S_LEN) { sacc[j][1] = -1e30f; sacc[j][3] = -1e30f; }
            }
        }

        // ---- online softmax ----
        float tm0 = -1e30f, tm1 = -1e30f;
#pragma unroll
        for (int j = 0; j < 8; j++) {
            tm0 = fmaxf(tm0, fmaxf(sacc[j][0], sacc[j][1]));
            tm1 = fmaxf(tm1, fmaxf(sacc[j][2], sacc[j][3]));
        }
        tm0 = fmaxf(tm0, __shfl_xor_sync(0xffffffffu, tm0, 1));
        tm0 = fmaxf(tm0, __shfl_xor_sync(0xffffffffu, tm0, 2));
        tm1 = fmaxf(tm1, __shfl_xor_sync(0xffffffffu, tm1, 1));
        tm1 = fmaxf(tm1, __shfl_xor_sync(0xffffffffu, tm1, 2));

        float nm0 = fmaxf(m0, tm0), nm1 = fmaxf(m1, tm1);
        float c0 = __expf(m0 - nm0), c1 = __expf(m1 - nm1);
        l0 *= c0; l1 *= c1;
#pragma unroll
        for (int j = 0; j < 8; j++) {
            of[j][0] *= c0; of[j][1] *= c0;
            of[j][2] *= c1; of[j][3] *= c1;
        }
        m0 = nm0; m1 = nm1;

        // ---- P = exp(S - m), tf32-rounded, kept in the sacc registers ----
        float ps0 = 0.f, ps1 = 0.f;
#pragma unroll
        for (int j = 0; j < 8; j++) {
            float p0 = rnd_tf(__expf(sacc[j][0] - nm0));
            float p1 = rnd_tf(__expf(sacc[j][1] - nm0));
            float p2 = rnd_tf(__expf(sacc[j][2] - nm1));
            float p3 = rnd_tf(__expf(sacc[j][3] - nm1));
            sacc[j][0] = p0; sacc[j][1] = p1; sacc[j][2] = p2; sacc[j][3] = p3;
            ps0 += p0 + p1; ps1 += p2 + p3;
        }
        ps0 += __shfl_xor_sync(0xffffffffu, ps0, 1);
        ps0 += __shfl_xor_sync(0xffffffffu, ps0, 2);
        ps1 += __shfl_xor_sync(0xffffffffu, ps1, 1);
        ps1 += __shfl_xor_sync(0xffffffffu, ps1, 2);
        l0 += ps0; l1 += ps1;

        // ---- O += P * V : A-fragment comes straight from sacc registers ----
#pragma unroll
        for (int ksJ = 0; ksJ < 8; ksJ++) {     // key block = S column block
            uint32_t af[4];
            af[0] = __float_as_uint(sacc[ksJ][0]);   // P[g   ][key 2t]
            af[1] = __float_as_uint(sacc[ksJ][2]);   // P[g+8 ][key 2t]
            af[2] = __float_as_uint(sacc[ksJ][1]);   // P[g   ][key 2t+1]
            af[3] = __float_as_uint(sacc[ksJ][3]);   // P[g+8 ][key 2t+1]
            const uint32_t* vrow = Vb + (ksJ * 8 + 2 * t) * VB_STRIDE + g;
#pragma unroll
            for (int j = 0; j < 8; j++) {
                uint32_t bf[2];
                bf[0] = vrow[j * 8];                 // V[key 2t  ][dim j8+g]
                bf[1] = vrow[VB_STRIDE + j * 8];     // V[key 2t+1][dim j8+g]
                mma_tf32(of[j], af, bf);
            }
        }
    }

    // ---- finalize + store (rounded: feeds O-proj as A operand) ----
    float inv0 = 1.0f / l0, inv1 = 1.0f / l1;
    int r0 = qrow0 + g, r1 = qrow0 + g + 8;
#pragma unroll
    for (int j = 0; j < 8; j++) {
        int c = h * D_HEAD + j * 8 + 2 * t;
        if (r0 < S_LEN)
            *(float2*)&out[(size_t)r0 * N_STATE + c] =
                make_float2(rnd_tf(of[j][0] * inv0), rnd_tf(of[j][1] * inv0));
        if (r1 < S_LEN)
            *(float2*)&out[(size_t)r1 * N_STATE + c] =
                make_float2(rnd_tf(of[j][2] * inv1), rnd_tf(of[j][3] * inv1));
    }
}

// ---------------------------------------------------------------------------
// Launch: 9 kernels on the default stream (graph-capturable, alloc-free)
// ---------------------------------------------------------------------------
extern "C" void kernel_launch(void* const* d_in, const int* in_sizes, int n_in,
                              void* d_out, int out_size) {
    (void)in_sizes; (void)n_in; (void)out_size;

    const float* x    = (const float*)d_in[0];
    const float* Wq   = (const float*)d_in[1];
    const float* bq   = (const float*)d_in[2];
    const float* Wk   = (const float*)d_in[3];
    const float* Wv   = (const float*)d_in[4];
    const float* bv   = (const float*)d_in[5];
    const float* Wo   = (const float*)d_in[6];
    const float* bo   = (const float*)d_in[7];
    const float* ln1g = (const float*)d_in[8];
    const float* ln1b = (const float*)d_in[9];
    const float* ln2g = (const float*)d_in[10];
    const float* ln2b = (const float*)d_in[11];
    const float* W1   = (const float*)d_in[12];
    const float* b1   = (const float*)d_in[13];
    const float* W2   = (const float*)d_in[14];
    const float* b2   = (const float*)d_in[15];
    float* out = (float*)d_out;

    Scratch* sc = nullptr;
    cudaGetSymbolAddress((void**)&sc, g_scratch);

    cudaFuncSetAttribute(gemm_tf32,
                         cudaFuncAttributeMaxDynamicSharedMemorySize,
                         GEMM_SMEM_BYTES);
    cudaFuncSetAttribute(attn_kernel,
                         cudaFuncAttributeMaxDynamicSharedMemorySize,
                         ATTN_SMEM_BYTES);

    dim3 gQKV (N_STATE / G_BN, (S_LEN + G_BM - 1) / G_BM, 3);  // (10,12,3)
    dim3 gSpl (N_STATE / G_BN, (S_LEN + G_BM - 1) / G_BM, 2);  // (10,12,2)
    dim3 gMLP1(N_MLP  / G_BN, (S_LEN + G_BM - 1) / G_BM, 1);   // (40,12,1)
    const int red_grid = (S_LEN * N_STATE / 4 + 255) / 256;

    // LN1 (output tf32-rounded)
    ln_kernel<<<S_LEN, 256>>>(x, ln1g, ln1b, sc->h);

    // QKV projections (one fused launch, shared A; outputs tf32-rounded)
    GemmBatch qkv;
    qkv.B[0] = Wq; qkv.bias[0] = bq;      qkv.C[0] = sc->q;
    qkv.B[1] = Wk; qkv.bias[1] = nullptr; qkv.C[1] = sc->k;
    qkv.B[2] = Wv; qkv.bias[2] = bv;      qkv.C[2] = sc->v;
    gemm_tf32<<<gQKV, 256, GEMM_SMEM_BYTES>>>(sc->h, qkv,
        S_LEN, N_STATE, N_STATE, /*lda=*/N_STATE, /*aOffK=*/0, 0, /*rnd=*/1);

    // attention (output tf32-rounded)
    attn_kernel<<<dim3(12, N_HEAD), 256, ATTN_SMEM_BYTES>>>(sc->q, sc->k, sc->v, sc->attn);

    // O-proj split-K x2 -> partials, then reduce (+bias +residual x) -> x1
    GemmBatch opr;
    opr.B[0] = Wo;                         opr.bias[0] = nullptr; opr.C[0] = sc->part0;
    opr.B[1] = Wo + (size_t)640 * N_STATE; opr.bias[1] = nullptr; opr.C[1] = sc->part1;
    opr.B[2] = nullptr; opr.bias[2] = nullptr; opr.C[2] = nullptr;
    gemm_tf32<<<gSpl, 256, GEMM_SMEM_BYTES>>>(sc->attn, opr,
        S_LEN, N_STATE, /*K=*/640, /*lda=*/N_STATE, /*aOffK=*/640, 0, 0);
    splitk_reduce<<<red_grid, 256>>>(sc->part0, sc->part1, bo, x, sc->x1);

    // LN2 (output tf32-rounded)
    ln_kernel<<<S_LEN, 256>>>(sc->x1, ln2g, ln2b, sc->h);

    // MLP1 (+exact GELU; output tf32-rounded)
    GemmBatch m1;
    m1.B[0] = W1; m1.bias[0] = b1; m1.C[0] = sc->h2;
    m1.B[1] = m1.B[2] = nullptr; m1.bias[1] = m1.bias[2] = nullptr;
    m1.C[1] = m1.C[2] = nullptr;
    gemm_tf32<<<gMLP1, 256, GEMM_SMEM_BYTES>>>(sc->h, m1,
        S_LEN, N_MLP, N_STATE, /*lda=*/N_STATE, /*aOffK=*/0, /*act=*/1, /*rnd=*/1);

    // MLP2 split-K x2 -> partials, then reduce (+bias +residual x1) -> out
    GemmBatch m2;
    m2.B[0] = W2;                          m2.bias[0] = nullptr; m2.C[0] = sc->part0;
    m2.B[1] = W2 + (size_t)2560 * N_STATE; m2.bias[1] = nullptr; m2.C[1] = sc->part1;
    m2.B[2] = nullptr; m2.bias[2] = nullptr; m2.C[2] = nullptr;
    gemm_tf32<<<gSpl, 256, GEMM_SMEM_BYTES>>>(sc->h2, m2,
        S_LEN, N_STATE, /*K=*/2560, /*lda=*/N_MLP, /*aOffK=*/2560, 0, 0);
    splitk_reduce<<<red_grid, 256>>>(sc->part0, sc->part1, b2, sc->x1, out);
}